// round 1
// baseline (speedup 1.0000x reference)
#include <cuda_runtime.h>
#include <math.h>

// Problem constants
#define B_  8
#define C_  512
#define N_  4096            // 64*64 spatial
#define K_  256             // key channels
#define V_  256             // value channels
#define O_  512             // out channels
#define BN_EPS 1e-5f
#define SIM_SCALE 0.0625f   // 256^-0.5

// Scratch (device globals: allocation-free per harness rules)
__device__ float g_val[(size_t)B_ * V_ * N_];          // 32 MB
__device__ float g_key[(size_t)B_ * K_ * N_];          // 32 MB
__device__ float g_ctx[(size_t)B_ * V_ * N_];          // 32 MB
__device__ float g_sim[(size_t)B_ * N_ * N_];          // 512 MB

// ---------------------------------------------------------------------------
// Shared SGEMM tile configuration: 64x64 output tile, K-step 16, 256 threads,
// 4x4 micro-tile per thread. smem row stride 68 floats (16B-aligned, low-conflict).
// ---------------------------------------------------------------------------
#define TS 64
#define KS 16
#define SMS 68

__device__ __forceinline__ void mm_inner(const float (*As)[SMS], const float (*Bs)[SMS],
                                         int ty, int tx, float acc[4][4]) {
#pragma unroll
    for (int kk = 0; kk < KS; ++kk) {
        float4 a = *(const float4*)&As[kk][ty * 4];
        float4 b = *(const float4*)&Bs[kk][tx * 4];
        acc[0][0] += a.x * b.x; acc[0][1] += a.x * b.y; acc[0][2] += a.x * b.z; acc[0][3] += a.x * b.w;
        acc[1][0] += a.y * b.x; acc[1][1] += a.y * b.y; acc[1][2] += a.y * b.z; acc[1][3] += a.y * b.w;
        acc[2][0] += a.z * b.x; acc[2][1] += a.z * b.y; acc[2][2] += a.z * b.z; acc[2][3] += a.z * b.w;
        acc[3][0] += a.w * b.x; acc[3][1] += a.w * b.y; acc[3][2] += a.w * b.z; acc[3][3] += a.w * b.w;
    }
}

// ---------------------------------------------------------------------------
// Kernel A: fused value + key projection.
// Combined C[512, 4096] = Wc[512, 512] @ x_b[512, 4096]; rows <256 -> value
// (+bias), rows >=256 -> key (+bias, BN inference, ReLU).
// grid (N/64, 512/64, B)
// ---------------------------------------------------------------------------
__global__ void kA_proj(const float* __restrict__ x,
                        const float* __restrict__ wv, const float* __restrict__ bv,
                        const float* __restrict__ wk, const float* __restrict__ bk,
                        const float* __restrict__ gamma, const float* __restrict__ beta,
                        const float* __restrict__ rmean, const float* __restrict__ rvar) {
    __shared__ float As[KS][SMS];
    __shared__ float Bs[KS][SMS];
    const int tid = threadIdx.x;
    const int ty = tid >> 4, tx = tid & 15;
    const int b = blockIdx.z;
    const int row0 = blockIdx.y * TS;       // combined output channel
    const int n0 = blockIdx.x * TS;
    const float* xb = x + (size_t)b * C_ * N_;

    float acc[4][4] = {};
    for (int k0 = 0; k0 < C_; k0 += KS) {
        // As[kk][r] = Wc[row0+r][k0+kk]
        for (int idx = tid; idx < KS * TS; idx += 256) {
            int kk = idx & 15, r = idx >> 4;
            int gr = row0 + r;
            float w = (gr < V_) ? wv[gr * C_ + k0 + kk] : wk[(gr - V_) * C_ + k0 + kk];
            As[kk][r] = w;
        }
        // Bs[kk][n] = x[b][k0+kk][n0+n]
        for (int idx = tid; idx < KS * TS; idx += 256) {
            int kk = idx >> 6, n = idx & 63;
            Bs[kk][n] = xb[(size_t)(k0 + kk) * N_ + n0 + n];
        }
        __syncthreads();
        mm_inner(As, Bs, ty, tx, acc);
        __syncthreads();
    }

    // Epilogue (whole block is either value or key since row tiles align to 256)
    if (row0 < V_) {
#pragma unroll
        for (int i = 0; i < 4; ++i) {
            int gr = row0 + ty * 4 + i;
            float bb = bv[gr];
            float* dst = &g_val[((size_t)b * V_ + gr) * N_ + n0 + tx * 4];
            float4 o = make_float4(acc[i][0] + bb, acc[i][1] + bb, acc[i][2] + bb, acc[i][3] + bb);
            *(float4*)dst = o;
        }
    } else {
#pragma unroll
        for (int i = 0; i < 4; ++i) {
            int r = row0 - V_ + ty * 4 + i;
            float s = gamma[r] * rsqrtf(rvar[r] + BN_EPS);
            float sh = beta[r] - (rmean[r] - bk[r]) * s;  // (acc+bk-rmean)*s+beta
            float4 o;
            o.x = fmaxf(acc[i][0] * s + sh, 0.f);
            o.y = fmaxf(acc[i][1] * s + sh, 0.f);
            o.z = fmaxf(acc[i][2] * s + sh, 0.f);
            o.w = fmaxf(acc[i][3] * s + sh, 0.f);
            float* dst = &g_key[((size_t)b * K_ + r) * N_ + n0 + tx * 4];
            *(float4*)dst = o;
        }
    }
}

// ---------------------------------------------------------------------------
// Kernel B: sim[n][m] = sum_k key[k][n] * key[k][m] * 2^-4
// grid (N/64 (m), N/64 (n), B)
// ---------------------------------------------------------------------------
__global__ void kB_sim() {
    __shared__ float As[KS][SMS];
    __shared__ float Bs[KS][SMS];
    const int tid = threadIdx.x;
    const int ty = tid >> 4, tx = tid & 15;
    const int b = blockIdx.z;
    const int n0 = blockIdx.y * TS;
    const int m0 = blockIdx.x * TS;
    const float* keyb = g_key + (size_t)b * K_ * N_;

    float acc[4][4] = {};
    for (int k0 = 0; k0 < K_; k0 += KS) {
        for (int idx = tid; idx < KS * TS; idx += 256) {
            int kk = idx >> 6, i = idx & 63;
            As[kk][i] = keyb[(size_t)(k0 + kk) * N_ + n0 + i];
        }
        for (int idx = tid; idx < KS * TS; idx += 256) {
            int kk = idx >> 6, j = idx & 63;
            Bs[kk][j] = keyb[(size_t)(k0 + kk) * N_ + m0 + j];
        }
        __syncthreads();
        mm_inner(As, Bs, ty, tx, acc);
        __syncthreads();
    }

    float* simb = g_sim + (size_t)b * N_ * N_;
#pragma unroll
    for (int i = 0; i < 4; ++i) {
        float* dst = &simb[(size_t)(n0 + ty * 4 + i) * N_ + m0 + tx * 4];
        float4 o = make_float4(acc[i][0] * SIM_SCALE, acc[i][1] * SIM_SCALE,
                               acc[i][2] * SIM_SCALE, acc[i][3] * SIM_SCALE);
        *(float4*)dst = o;
    }
}

// ---------------------------------------------------------------------------
// Kernel C: row softmax over sim (in place). grid (N, B), 256 threads.
// Each thread holds 16 elements (4x float4), two block reductions.
// ---------------------------------------------------------------------------
__global__ void kC_softmax() {
    const int tid = threadIdx.x;
    float* row = g_sim + ((size_t)blockIdx.y * N_ + blockIdx.x) * N_;
    float4* rowv = (float4*)row;

    float4 d[4];
    float mx = -1e30f;
#pragma unroll
    for (int c = 0; c < 4; ++c) {
        d[c] = rowv[c * 256 + tid];
        mx = fmaxf(mx, fmaxf(fmaxf(d[c].x, d[c].y), fmaxf(d[c].z, d[c].w)));
    }
    __shared__ float sred[8];
#pragma unroll
    for (int o = 16; o; o >>= 1) mx = fmaxf(mx, __shfl_xor_sync(0xffffffffu, mx, o));
    if ((tid & 31) == 0) sred[tid >> 5] = mx;
    __syncthreads();
    {
        float v = sred[tid & 7];
#pragma unroll
        for (int o = 4; o; o >>= 1) v = fmaxf(v, __shfl_xor_sync(0xffffffffu, v, o));
        mx = v;
    }
    __syncthreads();

    float sum = 0.f;
#pragma unroll
    for (int c = 0; c < 4; ++c) {
        d[c].x = __expf(d[c].x - mx); d[c].y = __expf(d[c].y - mx);
        d[c].z = __expf(d[c].z - mx); d[c].w = __expf(d[c].w - mx);
        sum += (d[c].x + d[c].y) + (d[c].z + d[c].w);
    }
#pragma unroll
    for (int o = 16; o; o >>= 1) sum += __shfl_xor_sync(0xffffffffu, sum, o);
    if ((tid & 31) == 0) sred[tid >> 5] = sum;
    __syncthreads();
    {
        float v = sred[tid & 7];
#pragma unroll
        for (int o = 4; o; o >>= 1) v += __shfl_xor_sync(0xffffffffu, v, o);
        sum = v;
    }
    float inv = __frcp_rn(sum);
#pragma unroll
    for (int c = 0; c < 4; ++c) {
        d[c].x *= inv; d[c].y *= inv; d[c].z *= inv; d[c].w *= inv;
        rowv[c * 256 + tid] = d[c];
    }
}

// ---------------------------------------------------------------------------
// Kernel D: ctx[v][n] = sum_m val[v][m] * sim[n][m]
// grid (N/64 (n), V/64 (v), B). Inner dim m is contiguous in both operands.
// ---------------------------------------------------------------------------
__global__ void kD_ctx() {
    __shared__ float As[KS][SMS];   // As[mm][v]
    __shared__ float Bs[KS][SMS];   // Bs[mm][n]
    const int tid = threadIdx.x;
    const int ty = tid >> 4, tx = tid & 15;
    const int b = blockIdx.z;
    const int v0 = blockIdx.y * TS;
    const int n0 = blockIdx.x * TS;
    const float* valb = g_val + (size_t)b * V_ * N_;
    const float* simb = g_sim + (size_t)b * N_ * N_;

    float acc[4][4] = {};
    for (int m0 = 0; m0 < N_; m0 += KS) {
        for (int idx = tid; idx < KS * TS; idx += 256) {
            int mm = idx & 15, vl = idx >> 4;
            As[mm][vl] = valb[(size_t)(v0 + vl) * N_ + m0 + mm];
        }
        for (int idx = tid; idx < KS * TS; idx += 256) {
            int mm = idx & 15, nl = idx >> 4;
            Bs[mm][nl] = simb[(size_t)(n0 + nl) * N_ + m0 + mm];
        }
        __syncthreads();
        mm_inner(As, Bs, ty, tx, acc);
        __syncthreads();
    }

#pragma unroll
    for (int i = 0; i < 4; ++i) {
        float* dst = &g_ctx[((size_t)b * V_ + v0 + ty * 4 + i) * N_ + n0 + tx * 4];
        *(float4*)dst = make_float4(acc[i][0], acc[i][1], acc[i][2], acc[i][3]);
    }
}

// ---------------------------------------------------------------------------
// Kernel E: out[o][n] = sum_v wW[o][v] * ctx[v][n] + bW[o]
// grid (N/64, O/64, B)
// ---------------------------------------------------------------------------
__global__ void kE_out(const float* __restrict__ wW, const float* __restrict__ bW,
                       float* __restrict__ out) {
    __shared__ float As[KS][SMS];
    __shared__ float Bs[KS][SMS];
    const int tid = threadIdx.x;
    const int ty = tid >> 4, tx = tid & 15;
    const int b = blockIdx.z;
    const int o0 = blockIdx.y * TS;
    const int n0 = blockIdx.x * TS;
    const float* ctxb = g_ctx + (size_t)b * V_ * N_;

    float acc[4][4] = {};
    for (int k0 = 0; k0 < V_; k0 += KS) {
        for (int idx = tid; idx < KS * TS; idx += 256) {
            int kk = idx & 15, r = idx >> 4;
            As[kk][r] = wW[(o0 + r) * V_ + k0 + kk];
        }
        for (int idx = tid; idx < KS * TS; idx += 256) {
            int kk = idx >> 6, n = idx & 63;
            Bs[kk][n] = ctxb[(size_t)(k0 + kk) * N_ + n0 + n];
        }
        __syncthreads();
        mm_inner(As, Bs, ty, tx, acc);
        __syncthreads();
    }

#pragma unroll
    for (int i = 0; i < 4; ++i) {
        int o = o0 + ty * 4 + i;
        float bb = bW[o];
        float* dst = &out[((size_t)b * O_ + o) * N_ + n0 + tx * 4];
        *(float4*)dst = make_float4(acc[i][0] + bb, acc[i][1] + bb, acc[i][2] + bb, acc[i][3] + bb);
    }
}

// ---------------------------------------------------------------------------
extern "C" void kernel_launch(void* const* d_in, const int* in_sizes, int n_in,
                              void* d_out, int out_size) {
    const float* x     = (const float*)d_in[0];
    const float* wv    = (const float*)d_in[1];
    const float* bv    = (const float*)d_in[2];
    const float* wk    = (const float*)d_in[3];
    const float* bk    = (const float*)d_in[4];
    const float* gamma = (const float*)d_in[5];
    const float* beta  = (const float*)d_in[6];
    const float* rmean = (const float*)d_in[7];
    const float* rvar  = (const float*)d_in[8];
    const float* wW    = (const float*)d_in[9];
    const float* bW    = (const float*)d_in[10];
    float* out = (float*)d_out;

    kA_proj<<<dim3(N_ / TS, (V_ + K_) / TS, B_), 256>>>(x, wv, bv, wk, bk,
                                                        gamma, beta, rmean, rvar);
    kB_sim<<<dim3(N_ / TS, N_ / TS, B_), 256>>>();
    kC_softmax<<<dim3(N_, B_), 256>>>();
    kD_ctx<<<dim3(N_ / TS, V_ / TS, B_), 256>>>();
    kE_out<<<dim3(N_ / TS, O_ / TS, B_), 256>>>(wW, bW, out);
}

// round 5
// speedup vs baseline: 2.4756x; 2.4756x over previous
#include <cuda_runtime.h>
#include <cuda_bf16.h>
#include <cstdint>
#include <math.h>

#define B_  8
#define C_  512
#define N_  4096
#define K_  256
#define V_  256
#define O_  512
#define BN_EPS 1e-5f
#define SIM_SCALE 0.0625f

// Scratch (device globals; allocation-free)
__device__ float g_val [(size_t)B_ * V_ * N_];     // [b][v][n]
__device__ float g_keyT[(size_t)B_ * N_ * K_];     // [b][n][k]
__device__ float g_ctxT[(size_t)B_ * N_ * V_];     // [b][n][v]
__device__ float g_sim [(size_t)B_ * N_ * N_];     // [b][n][m]

// smem: 2 stages x 4 planes (A_hi, A_lo, B_hi, B_lo) x 8KB = 64KB
#define OFF_AHI 0u
#define OFF_ALO 8192u
#define OFF_BHI 16384u
#define OFF_BLO 24576u
#define STAGE_SZ 32768u
#define SMEM_SZ 65536

__device__ __forceinline__ uint32_t smem_u32(const void* p) {
    uint32_t a;
    asm("{ .reg .u64 t; cvta.to.shared.u64 t, %1; cvt.u32.u64 %0, t; }" : "=r"(a) : "l"(p));
    return a;
}
__device__ __forceinline__ void ldsm4(uint32_t& r0, uint32_t& r1, uint32_t& r2, uint32_t& r3,
                                      uint32_t addr) {
    asm volatile("ldmatrix.sync.aligned.m8n8.x4.shared.b16 {%0,%1,%2,%3}, [%4];"
                 : "=r"(r0), "=r"(r1), "=r"(r2), "=r"(r3) : "r"(addr));
}
__device__ __forceinline__ void mma16816(float* c, uint32_t a0, uint32_t a1, uint32_t a2,
                                         uint32_t a3, uint32_t b0, uint32_t b1) {
    asm volatile(
        "mma.sync.aligned.m16n8k16.row.col.f32.bf16.bf16.f32 "
        "{%0,%1,%2,%3}, {%4,%5,%6,%7}, {%8,%9}, {%0,%1,%2,%3};"
        : "+f"(c[0]), "+f"(c[1]), "+f"(c[2]), "+f"(c[3])
        : "r"(a0), "r"(a1), "r"(a2), "r"(a3), "r"(b0), "r"(b1));
}
// split f32 pair -> packed bf16 hi + packed bf16 lo
__device__ __forceinline__ void cvt2(float x, float y, uint32_t& h, uint32_t& l) {
    __nv_bfloat162 hh = __floats2bfloat162_rn(x, y);
    float hx = __bfloat162float(hh.x), hy = __bfloat162float(hh.y);
    __nv_bfloat162 ll = __floats2bfloat162_rn(x - hx, y - hy);
    h = *(uint32_t*)&hh;
    l = *(uint32_t*)&ll;
}

// ---------------- loaders: gmem f32 tile [128 rows][32 k] -> smem bf16 hi/lo ----------------
// smem plane: row stride 64B, 16B chunks swizzled: chunk' = chunk ^ ((row>>1)&3)
struct LdK {       // k-contiguous rows
    const float* base;  // element ptr at (row0, k0); chunk ch advances k by 32
    int stride;         // row stride in elements
    float4 r[4];
    __device__ __forceinline__ void fetch(int ch, int tid) {
        const float* s = base + ch * 32;
#pragma unroll
        for (int t = 0; t < 2; ++t) {
            int task = tid + t * 256;           // 0..511
            int row = task >> 2, ck = task & 3;
            const float* p = s + (size_t)row * stride + ck * 8;
            r[2 * t]     = *(const float4*)p;
            r[2 * t + 1] = *(const float4*)(p + 4);
        }
    }
    __device__ __forceinline__ void store(char* smem, uint32_t hiOff, uint32_t loOff, int tid) {
#pragma unroll
        for (int t = 0; t < 2; ++t) {
            int task = tid + t * 256;
            int row = task >> 2, ck = task & 3;
            uint32_t off = (uint32_t)row * 64u + (uint32_t)((ck ^ ((row >> 1) & 3)) << 4);
            float4 a = r[2 * t], b = r[2 * t + 1];
            uint32_t h0, h1, h2, h3, l0, l1, l2, l3;
            cvt2(a.x, a.y, h0, l0); cvt2(a.z, a.w, h1, l1);
            cvt2(b.x, b.y, h2, l2); cvt2(b.z, b.w, h3, l3);
            *(uint4*)(smem + hiOff + off) = make_uint4(h0, h1, h2, h3);
            *(uint4*)(smem + loOff + off) = make_uint4(l0, l1, l2, l3);
        }
    }
};
struct LdT {       // transposing loader: src x[c][n] -> smem [n][c]
    const float* base;  // x + c0*N_ + n0 ; chunk ch advances c by 32
    float4 r[4];
    __device__ __forceinline__ void fetch(int ch, int tid) {
        const float* s = base + (size_t)(ch * 32) * N_;
#pragma unroll
        for (int t = 0; t < 4; ++t) {
            int task = tid + t * 256;           // 0..1023
            int cc = task >> 5, nq = task & 31;
            r[t] = *(const float4*)(s + (size_t)cc * N_ + nq * 4);
        }
    }
    __device__ __forceinline__ void store(char* smem, uint32_t hiOff, uint32_t loOff, int tid) {
#pragma unroll
        for (int t = 0; t < 4; ++t) {
            int task = tid + t * 256;
            int cc = task >> 5, nq = task & 31;
#pragma unroll
            for (int j = 0; j < 4; ++j) {
                int row = nq * 4 + j;
                float x = (&r[t].x)[j];
                __nv_bfloat16 h = __float2bfloat16_rn(x);
                __nv_bfloat16 l = __float2bfloat16_rn(x - __bfloat162float(h));
                uint32_t off = (uint32_t)row * 64u +
                               (uint32_t)(((cc >> 3) ^ ((row >> 1) & 3)) << 4) + (cc & 7) * 2;
                *(__nv_bfloat16*)(smem + hiOff + off) = h;
                *(__nv_bfloat16*)(smem + loOff + off) = l;
            }
        }
    }
};

// one bf16 product pass over a BK=32 chunk (2 k16 steps), 4 m-tiles x 4 n-tiles
__device__ __forceinline__ void mma_pass(uint32_t aBase, uint32_t bBase, uint32_t cb0,
                                         uint32_t cb1, float (&c)[4][4][4]) {
#pragma unroll
    for (int ks = 0; ks < 2; ++ks) {
        const uint32_t cb = ks ? cb1 : cb0;
        uint32_t a[4][4], b[2][4];
#pragma unroll
        for (int i = 0; i < 4; ++i)
            ldsm4(a[i][0], a[i][1], a[i][2], a[i][3], aBase + 1024u * i + cb);
#pragma unroll
        for (int p = 0; p < 2; ++p)
            ldsm4(b[p][0], b[p][1], b[p][2], b[p][3], bBase + 1024u * p + cb);
#pragma unroll
        for (int i = 0; i < 4; ++i)
#pragma unroll
            for (int j = 0; j < 4; ++j)
                mma16816(c[i][j], a[i][0], a[i][1], a[i][2], a[i][3],
                         b[j >> 1][j & 1], b[j >> 1][(j & 1) + 2]);
    }
}

template <class LA, class LB, class EP>
__device__ __forceinline__ void run_gemm(char* smem, int nc, LA& A, LB& Bv, EP ep) {
    const int tid = threadIdx.x;
    const int lane = tid & 31, wid = tid >> 5;
    const int wm0 = (wid >> 2) * 64, wn0 = (wid & 3) * 32;
    const int lr = lane & 15, lc = lane >> 4;
    const uint32_t sb = smem_u32(smem);
    const uint32_t sw = (uint32_t)((lr >> 1) & 3);
    const uint32_t cb0 = ((uint32_t)lc ^ sw) << 4;
    const uint32_t cb1 = ((uint32_t)(2 + lc) ^ sw) << 4;
    const uint32_t aRow = (uint32_t)(wm0 + lr) * 64u;
    const uint32_t bRow = (uint32_t)(wn0 + lr) * 64u;
    float c[4][4][4] = {};

    A.fetch(0, tid); Bv.fetch(0, tid);
    A.store(smem, OFF_AHI, OFF_ALO, tid); Bv.store(smem, OFF_BHI, OFF_BLO, tid);
    __syncthreads();
#pragma unroll 1
    for (int ch = 0; ch < nc; ++ch) {
        const uint32_t st = (ch & 1) ? STAGE_SZ : 0u;
        const bool more = (ch + 1 < nc);
        if (more) { A.fetch(ch + 1, tid); Bv.fetch(ch + 1, tid); }   // LDG under compute
        mma_pass(sb + st + OFF_AHI + aRow, sb + st + OFF_BHI + bRow, cb0, cb1, c);
        mma_pass(sb + st + OFF_AHI + aRow, sb + st + OFF_BLO + bRow, cb0, cb1, c);
        mma_pass(sb + st + OFF_ALO + aRow, sb + st + OFF_BHI + bRow, cb0, cb1, c);
        if (more) {
            const uint32_t ns = st ^ STAGE_SZ;
            A.store(smem, ns + OFF_AHI, ns + OFF_ALO, tid);
            Bv.store(smem, ns + OFF_BHI, ns + OFF_BLO, tid);
        }
        __syncthreads();
    }
    ep(c, wm0, wn0, lane);
}

// ---------------- Kernel A: fused value/key projection ----------------
__global__ void __launch_bounds__(256, 1)
kA(const float* __restrict__ x,
   const float* __restrict__ wv, const float* __restrict__ bv,
   const float* __restrict__ wk, const float* __restrict__ bk,
   const float* __restrict__ gamma, const float* __restrict__ beta,
   const float* __restrict__ rmean, const float* __restrict__ rvar) {
    extern __shared__ char smem[];
    const int b = blockIdx.z, n0 = blockIdx.x * 128, ch0 = blockIdx.y * 128;
    const float* wsrc = (ch0 < V_) ? (wv + (size_t)ch0 * C_) : (wk + (size_t)(ch0 - V_) * C_);
    LdK A{wsrc, C_};
    LdT Bv{x + (size_t)b * C_ * N_ + n0};

    auto ep = [&](float (&c)[4][4][4], int wm0, int wn0, int lane) {
        if (ch0 < V_) {
#pragma unroll
            for (int i = 0; i < 4; ++i) {
                int row = ch0 + wm0 + i * 16 + (lane >> 2);
                float b0 = bv[row], b1 = bv[row + 8];
                float* d0 = &g_val[((size_t)b * V_ + row) * N_ + n0];
                float* d1 = d0 + (size_t)8 * N_;
#pragma unroll
                for (int j = 0; j < 4; ++j) {
                    int col = wn0 + j * 8 + (lane & 3) * 2;
                    *(float2*)(d0 + col) = make_float2(c[i][j][0] + b0, c[i][j][1] + b0);
                    *(float2*)(d1 + col) = make_float2(c[i][j][2] + b1, c[i][j][3] + b1);
                }
            }
        } else {
#pragma unroll
            for (int i = 0; i < 4; ++i) {
                int r0 = ch0 - V_ + wm0 + i * 16 + (lane >> 2);
                int r1 = r0 + 8;
                float s0 = gamma[r0] * rsqrtf(rvar[r0] + BN_EPS);
                float h0 = beta[r0] - (rmean[r0] - bk[r0]) * s0;
                float s1 = gamma[r1] * rsqrtf(rvar[r1] + BN_EPS);
                float h1 = beta[r1] - (rmean[r1] - bk[r1]) * s1;
#pragma unroll
                for (int j = 0; j < 4; ++j) {
                    int col = n0 + wn0 + j * 8 + (lane & 3) * 2;
                    float* kb = g_keyT + ((size_t)b * N_ + col) * K_;
                    kb[r0]      = fmaxf(c[i][j][0] * s0 + h0, 0.f);
                    kb[K_ + r0] = fmaxf(c[i][j][1] * s0 + h0, 0.f);
                    kb[r1]      = fmaxf(c[i][j][2] * s1 + h1, 0.f);
                    kb[K_ + r1] = fmaxf(c[i][j][3] * s1 + h1, 0.f);
                }
            }
        }
    };
    run_gemm(smem, C_ / 32, A, Bv, ep);
}

// ---------------- Kernel B: sim = keyT . keyT^T * 1/16 ----------------
__global__ void __launch_bounds__(256, 1) kB() {
    extern __shared__ char smem[];
    const int b = blockIdx.z, m0 = blockIdx.x * 128, n0 = blockIdx.y * 128;
    const float* keyb = g_keyT + (size_t)b * N_ * K_;
    LdK A{keyb + (size_t)n0 * K_, K_};
    LdK Bv{keyb + (size_t)m0 * K_, K_};
    float* simb = g_sim + (size_t)b * N_ * N_;

    auto ep = [&](float (&c)[4][4][4], int wm0, int wn0, int lane) {
#pragma unroll
        for (int i = 0; i < 4; ++i) {
            int row = n0 + wm0 + i * 16 + (lane >> 2);
            float* d0 = simb + (size_t)row * N_ + m0;
            float* d1 = d0 + (size_t)8 * N_;
#pragma unroll
            for (int j = 0; j < 4; ++j) {
                int col = wn0 + j * 8 + (lane & 3) * 2;
                *(float2*)(d0 + col) = make_float2(c[i][j][0] * SIM_SCALE, c[i][j][1] * SIM_SCALE);
                *(float2*)(d1 + col) = make_float2(c[i][j][2] * SIM_SCALE, c[i][j][3] * SIM_SCALE);
            }
        }
    };
    run_gemm(smem, K_ / 32, A, Bv, ep);
}

// ---------------- Kernel C: row softmax (in place) ----------------
__global__ void kC_softmax() {
    const int tid = threadIdx.x;
    float* row = g_sim + ((size_t)blockIdx.y * N_ + blockIdx.x) * N_;
    float4* rowv = (float4*)row;
    float4 d[4];
    float mx = -1e30f;
#pragma unroll
    for (int c = 0; c < 4; ++c) {
        d[c] = rowv[c * 256 + tid];
        mx = fmaxf(mx, fmaxf(fmaxf(d[c].x, d[c].y), fmaxf(d[c].z, d[c].w)));
    }
    __shared__ float sred[8];
#pragma unroll
    for (int o = 16; o; o >>= 1) mx = fmaxf(mx, __shfl_xor_sync(0xffffffffu, mx, o));
    if ((tid & 31) == 0) sred[tid >> 5] = mx;
    __syncthreads();
    {
        float v = sred[tid & 7];
#pragma unroll
        for (int o = 4; o; o >>= 1) v = fmaxf(v, __shfl_xor_sync(0xffffffffu, v, o));
        mx = v;
    }
    __syncthreads();
    float sum = 0.f;
#pragma unroll
    for (int c = 0; c < 4; ++c) {
        d[c].x = __expf(d[c].x - mx); d[c].y = __expf(d[c].y - mx);
        d[c].z = __expf(d[c].z - mx); d[c].w = __expf(d[c].w - mx);
        sum += (d[c].x + d[c].y) + (d[c].z + d[c].w);
    }
#pragma unroll
    for (int o = 16; o; o >>= 1) sum += __shfl_xor_sync(0xffffffffu, sum, o);
    if ((tid & 31) == 0) sred[tid >> 5] = sum;
    __syncthreads();
    {
        float v = sred[tid & 7];
#pragma unroll
        for (int o = 4; o; o >>= 1) v += __shfl_xor_sync(0xffffffffu, v, o);
        sum = v;
    }
    float inv = __frcp_rn(sum);
#pragma unroll
    for (int c = 0; c < 4; ++c) {
        d[c].x *= inv; d[c].y *= inv; d[c].z *= inv; d[c].w *= inv;
        rowv[c * 256 + tid] = d[c];
    }
}

// ---------------- Kernel D: ctxT[n][v] = sum_m sim[n][m] * val[v][m] ----------------
__global__ void __launch_bounds__(256, 1) kD() {
    extern __shared__ char smem[];
    const int b = blockIdx.z, n0 = blockIdx.x * 128, v0 = blockIdx.y * 128;
    LdK A{g_sim + (size_t)b * N_ * N_ + (size_t)n0 * N_, N_};
    LdK Bv{g_val + (size_t)b * V_ * N_ + (size_t)v0 * N_, N_};

    auto ep = [&](float (&c)[4][4][4], int wm0, int wn0, int lane) {
#pragma unroll
        for (int i = 0; i < 4; ++i) {
            int row = n0 + wm0 + i * 16 + (lane >> 2);
            float* d0 = g_ctxT + ((size_t)b * N_ + row) * V_ + v0;
            float* d1 = d0 + (size_t)8 * V_;
#pragma unroll
            for (int j = 0; j < 4; ++j) {
                int col = wn0 + j * 8 + (lane & 3) * 2;
                *(float2*)(d0 + col) = make_float2(c[i][j][0], c[i][j][1]);
                *(float2*)(d1 + col) = make_float2(c[i][j][2], c[i][j][3]);
            }
        }
    };
    run_gemm(smem, N_ / 32, A, Bv, ep);
}

// ---------------- Kernel E: out[o][n] = wW . ctxT^T + bW ----------------
__global__ void __launch_bounds__(256, 1)
kE(const float* __restrict__ wW, const float* __restrict__ bW, float* __restrict__ out) {
    extern __shared__ char smem[];
    const int b = blockIdx.z, n0 = blockIdx.x * 128, o0 = blockIdx.y * 128;
    LdK A{wW + (size_t)o0 * V_, V_};
    LdK Bv{g_ctxT + (size_t)b * N_ * V_ + (size_t)n0 * V_, V_};

    auto ep = [&](float (&c)[4][4][4], int wm0, int wn0, int lane) {
#pragma unroll
        for (int i = 0; i < 4; ++i) {
            int row = o0 + wm0 + i * 16 + (lane >> 2);
            float b0 = bW[row], b1 = bW[row + 8];
            float* d0 = out + ((size_t)b * O_ + row) * N_ + n0;
            float* d1 = d0 + (size_t)8 * N_;
#pragma unroll
            for (int j = 0; j < 4; ++j) {
                int col = wn0 + j * 8 + (lane & 3) * 2;
                *(float2*)(d0 + col) = make_float2(c[i][j][0] + b0, c[i][j][1] + b0);
                *(float2*)(d1 + col) = make_float2(c[i][j][2] + b1, c[i][j][3] + b1);
            }
        }
    };
    run_gemm(smem, V_ / 32, A, Bv, ep);
}

// ---------------------------------------------------------------------------
extern "C" void kernel_launch(void* const* d_in, const int* in_sizes, int n_in,
                              void* d_out, int out_size) {
    const float* x     = (const float*)d_in[0];
    const float* wv    = (const float*)d_in[1];
    const float* bv    = (const float*)d_in[2];
    const float* wk    = (const float*)d_in[3];
    const float* bk    = (const float*)d_in[4];
    const float* gamma = (const float*)d_in[5];
    const float* beta  = (const float*)d_in[6];
    const float* rmean = (const float*)d_in[7];
    const float* rvar  = (const float*)d_in[8];
    const float* wW    = (const float*)d_in[9];
    const float* bW    = (const float*)d_in[10];
    float* out = (float*)d_out;

    cudaFuncSetAttribute(kA, cudaFuncAttributeMaxDynamicSharedMemorySize, SMEM_SZ);
    cudaFuncSetAttribute(kB, cudaFuncAttributeMaxDynamicSharedMemorySize, SMEM_SZ);
    cudaFuncSetAttribute(kD, cudaFuncAttributeMaxDynamicSharedMemorySize, SMEM_SZ);
    cudaFuncSetAttribute(kE, cudaFuncAttributeMaxDynamicSharedMemorySize, SMEM_SZ);

    kA<<<dim3(N_ / 128, (V_ + K_) / 128, B_), 256, SMEM_SZ>>>(x, wv, bv, wk, bk,
                                                              gamma, beta, rmean, rvar);
    kB<<<dim3(N_ / 128, N_ / 128, B_), 256, SMEM_SZ>>>();
    kC_softmax<<<dim3(N_, B_), 256>>>();
    kD<<<dim3(N_ / 128, V_ / 128, B_), 256, SMEM_SZ>>>();
    kE<<<dim3(N_ / 128, O_ / 128, B_), 256, SMEM_SZ>>>(wW, bW, out);
}

// round 10
// speedup vs baseline: 3.2065x; 1.2952x over previous
#include <cuda_runtime.h>
#include <cuda_bf16.h>
#include <cstdint>
#include <math.h>

#define B_  8
#define C_  512
#define N_  4096
#define K_  256
#define V_  256
#define O_  512
#define BN_EPS 1e-5f
#define SIM_SCALE 0.0625f

typedef __nv_bfloat16  bf16;
typedef __nv_bfloat162 bf162;

// ---------------- device scratch (allocation-free) ----------------
__device__ __align__(256) bf16  g_val_hi[(size_t)B_ * V_ * N_];   // [b][v][n]
__device__ __align__(256) bf16  g_val_lo[(size_t)B_ * V_ * N_];
__device__ __align__(256) bf16  g_key_hi[(size_t)B_ * N_ * K_];   // [b][n][k]
__device__ __align__(256) bf16  g_key_lo[(size_t)B_ * N_ * K_];
__device__ __align__(256) bf16  g_ctx_hi[(size_t)B_ * N_ * V_];   // [b][n][v]
__device__ __align__(256) bf16  g_ctx_lo[(size_t)B_ * N_ * V_];
__device__ __align__(256) bf16  g_simh [(size_t)B_ * N_ * N_];    // [b][n][m] softmaxed
__device__ __align__(256) bf16  g_siml [(size_t)B_ * N_ * N_];
__device__ __align__(256) float g_sim  [(size_t)B_ * N_ * N_];    // [b][n][m] logits
__device__ __align__(256) bf16  g_wW_hi[O_ * V_];
__device__ __align__(256) bf16  g_wW_lo[O_ * V_];

// ---------------- common PTX helpers ----------------
__device__ __forceinline__ uint32_t smem_u32(const void* p) {
    uint32_t a;
    asm("{ .reg .u64 t; cvta.to.shared.u64 t, %1; cvt.u32.u64 %0, t; }" : "=r"(a) : "l"(p));
    return a;
}
__device__ __forceinline__ void ldsm4(uint32_t& r0, uint32_t& r1, uint32_t& r2, uint32_t& r3,
                                      uint32_t addr) {
    asm volatile("ldmatrix.sync.aligned.m8n8.x4.shared.b16 {%0,%1,%2,%3}, [%4];"
                 : "=r"(r0), "=r"(r1), "=r"(r2), "=r"(r3) : "r"(addr));
}
__device__ __forceinline__ void mma16816(float* c, uint32_t a0, uint32_t a1, uint32_t a2,
                                         uint32_t a3, uint32_t b0, uint32_t b1) {
    asm volatile(
        "mma.sync.aligned.m16n8k16.row.col.f32.bf16.bf16.f32 "
        "{%0,%1,%2,%3}, {%4,%5,%6,%7}, {%8,%9}, {%0,%1,%2,%3};"
        : "+f"(c[0]), "+f"(c[1]), "+f"(c[2]), "+f"(c[3])
        : "r"(a0), "r"(a1), "r"(a2), "r"(a3), "r"(b0), "r"(b1));
}
__device__ __forceinline__ void cpa16(uint32_t dst, const void* src) {
    asm volatile("cp.async.cg.shared.global [%0], [%1], 16;" :: "r"(dst), "l"(src));
}
// split f32 pair -> packed bf16 hi + packed bf16 lo
__device__ __forceinline__ void split2(float x, float y, bf162& h, bf162& l) {
    h = __floats2bfloat162_rn(x, y);
    l = __floats2bfloat162_rn(x - __bfloat162float(h.x), y - __bfloat162float(h.y));
}
__device__ __forceinline__ void cvt2(float x, float y, uint32_t& h, uint32_t& l) {
    bf162 hh, ll;
    split2(x, y, hh, ll);
    h = *(uint32_t*)&hh;
    l = *(uint32_t*)&ll;
}

// ===========================================================================
// Async GEMM core: 128x128 tile, BK=32, operands are pre-split bf16 hi/lo
// planes in gmem, row-major [row][k], k contiguous. 3-stage cp.async pipe.
// smem stage: AHI(8K) ALO(8K) BHI(8K) BLO(8K) = 32KB; 3 stages = 96KB.
// ===========================================================================
#define ASTAGE 32768u
#define ASMEM  98304

template <class EP>
__device__ __forceinline__ void run_gemm_async(
        char* smem, int nc,
        const bf16* __restrict__ aH, const bf16* __restrict__ aL, int as,
        const bf16* __restrict__ bH, const bf16* __restrict__ bL, int bs, EP ep) {
    const int tid = threadIdx.x;
    const int lane = tid & 31, wid = tid >> 5;
    const int wm0 = (wid >> 2) * 64, wn0 = (wid & 3) * 32;
    const int lr = lane & 15, lc = lane >> 4;
    const uint32_t sb = smem_u32(smem);
    const uint32_t sw = (uint32_t)((lr >> 1) & 3);
    const uint32_t cb0 = ((uint32_t)lc ^ sw) << 4;
    const uint32_t cb1 = ((uint32_t)(2 + lc) ^ sw) << 4;
    const uint32_t aRow = (uint32_t)(wm0 + lr) * 64u;
    const uint32_t bRow = (uint32_t)(wn0 + lr) * 64u;
    float c[4][4][4] = {};

    // copy indexing: each thread moves one 16B chunk per plane-half
    const int r0 = tid >> 2, ck = tid & 3;
    const uint32_t dsw0 = (uint32_t)r0 * 64u + (uint32_t)((ck ^ ((r0 >> 1) & 3)) << 4);
    // rows 64..127 share swizzle phase: dsw1 = dsw0 + 64*64
    const bf16* a0 = aH + (size_t)r0 * as + ck * 8;
    const bf16* a1 = aL + (size_t)r0 * as + ck * 8;
    const bf16* b0 = bH + (size_t)r0 * bs + ck * 8;
    const bf16* b1 = bL + (size_t)r0 * bs + ck * 8;

    auto copy = [&](int ch, int stage) {
        const uint32_t st = sb + (uint32_t)stage * ASTAGE;
        const int ko = ch * 32;
        cpa16(st + dsw0,           a0 + ko);
        cpa16(st + dsw0 + 4096u,   a0 + ko + (size_t)64 * as);
        cpa16(st + 8192u  + dsw0,          a1 + ko);
        cpa16(st + 8192u  + dsw0 + 4096u,  a1 + ko + (size_t)64 * as);
        cpa16(st + 16384u + dsw0,          b0 + ko);
        cpa16(st + 16384u + dsw0 + 4096u,  b0 + ko + (size_t)64 * bs);
        cpa16(st + 24576u + dsw0,          b1 + ko);
        cpa16(st + 24576u + dsw0 + 4096u,  b1 + ko + (size_t)64 * bs);
        asm volatile("cp.async.commit_group;");
    };

    auto compute = [&](int stage) {
        const uint32_t st = sb + (uint32_t)stage * ASTAGE;
        const uint32_t ah = st + aRow, al = st + 8192u + aRow;
        const uint32_t bh = st + 16384u + bRow, bl = st + 24576u + bRow;
#pragma unroll
        for (int ks = 0; ks < 2; ++ks) {
            const uint32_t cb = ks ? cb1 : cb0;
            uint32_t AH[4][4], AL[4][4], BH[2][4], BL[2][4];
#pragma unroll
            for (int i = 0; i < 4; ++i)
                ldsm4(AH[i][0], AH[i][1], AH[i][2], AH[i][3], ah + 1024u * i + cb);
#pragma unroll
            for (int p = 0; p < 2; ++p)
                ldsm4(BH[p][0], BH[p][1], BH[p][2], BH[p][3], bh + 1024u * p + cb);
#pragma unroll
            for (int i = 0; i < 4; ++i)
                ldsm4(AL[i][0], AL[i][1], AL[i][2], AL[i][3], al + 1024u * i + cb);
#pragma unroll
            for (int p = 0; p < 2; ++p)
                ldsm4(BL[p][0], BL[p][1], BL[p][2], BL[p][3], bl + 1024u * p + cb);
#pragma unroll
            for (int i = 0; i < 4; ++i)
#pragma unroll
                for (int j = 0; j < 4; ++j) {
                    const uint32_t bh0 = BH[j >> 1][j & 1], bh1 = BH[j >> 1][(j & 1) + 2];
                    const uint32_t bl0 = BL[j >> 1][j & 1], bl1 = BL[j >> 1][(j & 1) + 2];
                    mma16816(c[i][j], AH[i][0], AH[i][1], AH[i][2], AH[i][3], bh0, bh1);
                    mma16816(c[i][j], AH[i][0], AH[i][1], AH[i][2], AH[i][3], bl0, bl1);
                    mma16816(c[i][j], AL[i][0], AL[i][1], AL[i][2], AL[i][3], bh0, bh1);
                }
        }
    };

    copy(0, 0);
    copy(1, 1);
#pragma unroll 1
    for (int ch = 0; ch < nc; ++ch) {
        if (ch + 1 < nc) asm volatile("cp.async.wait_group 1;" ::: "memory");
        else             asm volatile("cp.async.wait_group 0;" ::: "memory");
        __syncthreads();
        if (ch + 2 < nc) copy(ch + 2, (ch + 2) % 3);
        compute(ch % 3);
    }
    ep(c, wm0, wn0, lane);
}

// ===========================================================================
// f32-input GEMM core (kA only): 2-stage, converts f32->hi/lo during fill
// ===========================================================================
#define OFF_AHI 0u
#define OFF_ALO 8192u
#define OFF_BHI 16384u
#define OFF_BLO 24576u
#define STAGE_SZ 32768u
#define SMEM_SZ 65536

struct LdK {
    const float* base;
    int stride;
    float4 r[4];
    __device__ __forceinline__ void fetch(int ch, int tid) {
        const float* s = base + ch * 32;
#pragma unroll
        for (int t = 0; t < 2; ++t) {
            int task = tid + t * 256;
            int row = task >> 2, ck = task & 3;
            const float* p = s + (size_t)row * stride + ck * 8;
            r[2 * t]     = *(const float4*)p;
            r[2 * t + 1] = *(const float4*)(p + 4);
        }
    }
    __device__ __forceinline__ void store(char* smem, uint32_t hiOff, uint32_t loOff, int tid) {
#pragma unroll
        for (int t = 0; t < 2; ++t) {
            int task = tid + t * 256;
            int row = task >> 2, ck = task & 3;
            uint32_t off = (uint32_t)row * 64u + (uint32_t)((ck ^ ((row >> 1) & 3)) << 4);
            float4 a = r[2 * t], b = r[2 * t + 1];
            uint32_t h0, h1, h2, h3, l0, l1, l2, l3;
            cvt2(a.x, a.y, h0, l0); cvt2(a.z, a.w, h1, l1);
            cvt2(b.x, b.y, h2, l2); cvt2(b.z, b.w, h3, l3);
            *(uint4*)(smem + hiOff + off) = make_uint4(h0, h1, h2, h3);
            *(uint4*)(smem + loOff + off) = make_uint4(l0, l1, l2, l3);
        }
    }
};
struct LdT {
    const float* base;
    float4 r[4];
    __device__ __forceinline__ void fetch(int ch, int tid) {
        const float* s = base + (size_t)(ch * 32) * N_;
#pragma unroll
        for (int t = 0; t < 4; ++t) {
            int task = tid + t * 256;
            int cc = task >> 5, nq = task & 31;
            r[t] = *(const float4*)(s + (size_t)cc * N_ + nq * 4);
        }
    }
    __device__ __forceinline__ void store(char* smem, uint32_t hiOff, uint32_t loOff, int tid) {
#pragma unroll
        for (int t = 0; t < 4; ++t) {
            int task = tid + t * 256;
            int cc = task >> 5, nq = task & 31;
#pragma unroll
            for (int j = 0; j < 4; ++j) {
                int row = nq * 4 + j;
                float x = (&r[t].x)[j];
                bf16 h = __float2bfloat16_rn(x);
                bf16 l = __float2bfloat16_rn(x - __bfloat162float(h));
                uint32_t off = (uint32_t)row * 64u +
                               (uint32_t)(((cc >> 3) ^ ((row >> 1) & 3)) << 4) + (cc & 7) * 2;
                *(bf16*)(smem + hiOff + off) = h;
                *(bf16*)(smem + loOff + off) = l;
            }
        }
    }
};

__device__ __forceinline__ void mma_pass(uint32_t aBase, uint32_t bBase, uint32_t cb0,
                                         uint32_t cb1, float (&c)[4][4][4]) {
#pragma unroll
    for (int ks = 0; ks < 2; ++ks) {
        const uint32_t cb = ks ? cb1 : cb0;
        uint32_t a[4][4], b[2][4];
#pragma unroll
        for (int i = 0; i < 4; ++i)
            ldsm4(a[i][0], a[i][1], a[i][2], a[i][3], aBase + 1024u * i + cb);
#pragma unroll
        for (int p = 0; p < 2; ++p)
            ldsm4(b[p][0], b[p][1], b[p][2], b[p][3], bBase + 1024u * p + cb);
#pragma unroll
        for (int i = 0; i < 4; ++i)
#pragma unroll
            for (int j = 0; j < 4; ++j)
                mma16816(c[i][j], a[i][0], a[i][1], a[i][2], a[i][3],
                         b[j >> 1][j & 1], b[j >> 1][(j & 1) + 2]);
    }
}

template <class LA, class LB, class EP>
__device__ __forceinline__ void run_gemm(char* smem, int nc, LA& A, LB& Bv, EP ep) {
    const int tid = threadIdx.x;
    const int lane = tid & 31, wid = tid >> 5;
    const int wm0 = (wid >> 2) * 64, wn0 = (wid & 3) * 32;
    const int lr = lane & 15, lc = lane >> 4;
    const uint32_t sb = smem_u32(smem);
    const uint32_t sw = (uint32_t)((lr >> 1) & 3);
    const uint32_t cb0 = ((uint32_t)lc ^ sw) << 4;
    const uint32_t cb1 = ((uint32_t)(2 + lc) ^ sw) << 4;
    const uint32_t aRow = (uint32_t)(wm0 + lr) * 64u;
    const uint32_t bRow = (uint32_t)(wn0 + lr) * 64u;
    float c[4][4][4] = {};

    A.fetch(0, tid); Bv.fetch(0, tid);
    A.store(smem, OFF_AHI, OFF_ALO, tid); Bv.store(smem, OFF_BHI, OFF_BLO, tid);
    __syncthreads();
#pragma unroll 1
    for (int ch = 0; ch < nc; ++ch) {
        const uint32_t st = (ch & 1) ? STAGE_SZ : 0u;
        const bool more = (ch + 1 < nc);
        if (more) { A.fetch(ch + 1, tid); Bv.fetch(ch + 1, tid); }
        mma_pass(sb + st + OFF_AHI + aRow, sb + st + OFF_BHI + bRow, cb0, cb1, c);
        mma_pass(sb + st + OFF_AHI + aRow, sb + st + OFF_BLO + bRow, cb0, cb1, c);
        mma_pass(sb + st + OFF_ALO + aRow, sb + st + OFF_BHI + bRow, cb0, cb1, c);
        if (more) {
            const uint32_t ns = st ^ STAGE_SZ;
            A.store(smem, ns + OFF_AHI, ns + OFF_ALO, tid);
            Bv.store(smem, ns + OFF_BHI, ns + OFF_BLO, tid);
        }
        __syncthreads();
    }
    ep(c, wm0, wn0, lane);
}

// ---------------- kW: pre-split wW into bf16 hi/lo planes ----------------
__global__ void kW(const float* __restrict__ w) {
    int i = blockIdx.x * 256 + threadIdx.x;
    float x = w[i];
    bf16 h = __float2bfloat16_rn(x);
    g_wW_hi[i] = h;
    g_wW_lo[i] = __float2bfloat16_rn(x - __bfloat162float(h));
}

// ---------------- Kernel A: fused value/key projection ----------------
__global__ void __launch_bounds__(256, 1)
kA(const float* __restrict__ x,
   const float* __restrict__ wv, const float* __restrict__ bv,
   const float* __restrict__ wk, const float* __restrict__ bk,
   const float* __restrict__ gamma, const float* __restrict__ beta,
   const float* __restrict__ rmean, const float* __restrict__ rvar) {
    extern __shared__ char smem[];
    const int b = blockIdx.z, n0 = blockIdx.x * 128, ch0 = blockIdx.y * 128;
    const float* wsrc = (ch0 < V_) ? (wv + (size_t)ch0 * C_) : (wk + (size_t)(ch0 - V_) * C_);
    LdK A{wsrc, C_};
    LdT Bv{x + (size_t)b * C_ * N_ + n0};

    auto ep = [&](float (&c)[4][4][4], int wm0, int wn0, int lane) {
        if (ch0 < V_) {
#pragma unroll
            for (int i = 0; i < 4; ++i) {
                int row = ch0 + wm0 + i * 16 + (lane >> 2);
                float b0 = bv[row], b1 = bv[row + 8];
                size_t d0 = ((size_t)b * V_ + row) * N_ + n0;
                size_t d1 = d0 + (size_t)8 * N_;
#pragma unroll
                for (int j = 0; j < 4; ++j) {
                    int col = wn0 + j * 8 + (lane & 3) * 2;
                    bf162 h, l;
                    split2(c[i][j][0] + b0, c[i][j][1] + b0, h, l);
                    *(bf162*)(g_val_hi + d0 + col) = h;
                    *(bf162*)(g_val_lo + d0 + col) = l;
                    split2(c[i][j][2] + b1, c[i][j][3] + b1, h, l);
                    *(bf162*)(g_val_hi + d1 + col) = h;
                    *(bf162*)(g_val_lo + d1 + col) = l;
                }
            }
        } else {
#pragma unroll
            for (int i = 0; i < 4; ++i) {
                int r0 = ch0 - V_ + wm0 + i * 16 + (lane >> 2);
                int r1 = r0 + 8;
                float s0 = gamma[r0] * rsqrtf(rvar[r0] + BN_EPS);
                float h0 = beta[r0] - (rmean[r0] - bk[r0]) * s0;
                float s1 = gamma[r1] * rsqrtf(rvar[r1] + BN_EPS);
                float h1 = beta[r1] - (rmean[r1] - bk[r1]) * s1;
#pragma unroll
                for (int j = 0; j < 4; ++j) {
                    int col = n0 + wn0 + j * 8 + (lane & 3) * 2;
                    size_t kb = ((size_t)b * N_ + col) * K_;
                    float v00 = fmaxf(c[i][j][0] * s0 + h0, 0.f);
                    float v01 = fmaxf(c[i][j][1] * s0 + h0, 0.f);
                    float v10 = fmaxf(c[i][j][2] * s1 + h1, 0.f);
                    float v11 = fmaxf(c[i][j][3] * s1 + h1, 0.f);
                    bf16 t;
                    t = __float2bfloat16_rn(v00); g_key_hi[kb + r0] = t;
                    g_key_lo[kb + r0] = __float2bfloat16_rn(v00 - __bfloat162float(t));
                    t = __float2bfloat16_rn(v01); g_key_hi[kb + K_ + r0] = t;
                    g_key_lo[kb + K_ + r0] = __float2bfloat16_rn(v01 - __bfloat162float(t));
                    t = __float2bfloat16_rn(v10); g_key_hi[kb + r1] = t;
                    g_key_lo[kb + r1] = __float2bfloat16_rn(v10 - __bfloat162float(t));
                    t = __float2bfloat16_rn(v11); g_key_hi[kb + K_ + r1] = t;
                    g_key_lo[kb + K_ + r1] = __float2bfloat16_rn(v11 - __bfloat162float(t));
                }
            }
        }
    };
    run_gemm(smem, C_ / 32, A, Bv, ep);
}

// ---------------- Kernel B: sim = keyT . keyT^T * 1/16 (async) ----------------
__global__ void __launch_bounds__(256, 1) kB() {
    extern __shared__ char smem[];
    const int b = blockIdx.z, m0 = blockIdx.x * 128, n0 = blockIdx.y * 128;
    const size_t kb = (size_t)b * N_ * K_;
    float* simb = g_sim + (size_t)b * N_ * N_;

    auto ep = [&](float (&c)[4][4][4], int wm0, int wn0, int lane) {
#pragma unroll
        for (int i = 0; i < 4; ++i) {
            int row = n0 + wm0 + i * 16 + (lane >> 2);
            float* d0 = simb + (size_t)row * N_ + m0;
            float* d1 = d0 + (size_t)8 * N_;
#pragma unroll
            for (int j = 0; j < 4; ++j) {
                int col = wn0 + j * 8 + (lane & 3) * 2;
                *(float2*)(d0 + col) = make_float2(c[i][j][0] * SIM_SCALE, c[i][j][1] * SIM_SCALE);
                *(float2*)(d1 + col) = make_float2(c[i][j][2] * SIM_SCALE, c[i][j][3] * SIM_SCALE);
            }
        }
    };
    run_gemm_async(smem, K_ / 32,
                   g_key_hi + kb + (size_t)n0 * K_, g_key_lo + kb + (size_t)n0 * K_, K_,
                   g_key_hi + kb + (size_t)m0 * K_, g_key_lo + kb + (size_t)m0 * K_, K_, ep);
}

// ---------------- Kernel C: row softmax, f32 in, bf16 hi/lo out ----------------
__global__ void kC_softmax() {
    const int tid = threadIdx.x;
    const size_t rowo = ((size_t)blockIdx.y * N_ + blockIdx.x) * N_;
    const float4* rowv = (const float4*)(g_sim + rowo);

    float4 d[4];
    float mx = -1e30f;
#pragma unroll
    for (int c = 0; c < 4; ++c) {
        d[c] = rowv[c * 256 + tid];
        mx = fmaxf(mx, fmaxf(fmaxf(d[c].x, d[c].y), fmaxf(d[c].z, d[c].w)));
    }
    __shared__ float sred[8];
#pragma unroll
    for (int o = 16; o; o >>= 1) mx = fmaxf(mx, __shfl_xor_sync(0xffffffffu, mx, o));
    if ((tid & 31) == 0) sred[tid >> 5] = mx;
    __syncthreads();
    {
        float v = sred[tid & 7];
#pragma unroll
        for (int o = 4; o; o >>= 1) v = fmaxf(v, __shfl_xor_sync(0xffffffffu, v, o));
        mx = v;
    }
    __syncthreads();
    float sum = 0.f;
#pragma unroll
    for (int c = 0; c < 4; ++c) {
        d[c].x = __expf(d[c].x - mx); d[c].y = __expf(d[c].y - mx);
        d[c].z = __expf(d[c].z - mx); d[c].w = __expf(d[c].w - mx);
        sum += (d[c].x + d[c].y) + (d[c].z + d[c].w);
    }
#pragma unroll
    for (int o = 16; o; o >>= 1) sum += __shfl_xor_sync(0xffffffffu, sum, o);
    if ((tid & 31) == 0) sred[tid >> 5] = sum;
    __syncthreads();
    {
        float v = sred[tid & 7];
#pragma unroll
        for (int o = 4; o; o >>= 1) v += __shfl_xor_sync(0xffffffffu, v, o);
        sum = v;
    }
    float inv = __frcp_rn(sum);
    bf16* rh = g_simh + rowo;
    bf16* rl = g_siml + rowo;
#pragma unroll
    for (int c = 0; c < 4; ++c) {
        int idx = (c * 256 + tid) * 4;
        float p0 = d[c].x * inv, p1 = d[c].y * inv, p2 = d[c].z * inv, p3 = d[c].w * inv;
        bf162 h0, l0, h1, l1;
        split2(p0, p1, h0, l0);
        split2(p2, p3, h1, l1);
        *(bf162*)(rh + idx)     = h0;
        *(bf162*)(rh + idx + 2) = h1;
        *(bf162*)(rl + idx)     = l0;
        *(bf162*)(rl + idx + 2) = l1;
    }
}

// ---------------- Kernel D: ctxT[n][v] = sum_m sim[n][m]*val[v][m] (async) ----------------
__global__ void __launch_bounds__(256, 1) kD() {
    extern __shared__ char smem[];
    const int b = blockIdx.z, n0 = blockIdx.x * 128, v0 = blockIdx.y * 128;
    const size_t so = (size_t)b * N_ * N_ + (size_t)n0 * N_;
    const size_t vo = (size_t)b * V_ * N_ + (size_t)v0 * N_;

    auto ep = [&](float (&c)[4][4][4], int wm0, int wn0, int lane) {
#pragma unroll
        for (int i = 0; i < 4; ++i) {
            int row = n0 + wm0 + i * 16 + (lane >> 2);
            size_t d0 = ((size_t)b * N_ + row) * V_ + v0;
            size_t d1 = d0 + (size_t)8 * V_;
#pragma unroll
            for (int j = 0; j < 4; ++j) {
                int col = wn0 + j * 8 + (lane & 3) * 2;
                bf162 h, l;
                split2(c[i][j][0], c[i][j][1], h, l);
                *(bf162*)(g_ctx_hi + d0 + col) = h;
                *(bf162*)(g_ctx_lo + d0 + col) = l;
                split2(c[i][j][2], c[i][j][3], h, l);
                *(bf162*)(g_ctx_hi + d1 + col) = h;
                *(bf162*)(g_ctx_lo + d1 + col) = l;
            }
        }
    };
    run_gemm_async(smem, N_ / 32,
                   g_simh + so, g_siml + so, N_,
                   g_val_hi + vo, g_val_lo + vo, N_, ep);
}

// ---------------- Kernel E: out = wW . ctxT^T + bW (async) ----------------
__global__ void __launch_bounds__(256, 1)
kE(const float* __restrict__ bW, float* __restrict__ out) {
    extern __shared__ char smem[];
    const int b = blockIdx.z, n0 = blockIdx.x * 128, o0 = blockIdx.y * 128;
    const size_t co = (size_t)b * N_ * V_ + (size_t)n0 * V_;

    auto ep = [&](float (&c)[4][4][4], int wm0, int wn0, int lane) {
#pragma unroll
        for (int i = 0; i < 4; ++i) {
            int row = o0 + wm0 + i * 16 + (lane >> 2);
            float b0 = bW[row], b1 = bW[row + 8];
            float* d0 = out + ((size_t)b * O_ + row) * N_ + n0;
            float* d1 = d0 + (size_t)8 * N_;
#pragma unroll
            for (int j = 0; j < 4; ++j) {
                int col = wn0 + j * 8 + (lane & 3) * 2;
                *(float2*)(d0 + col) = make_float2(c[i][j][0] + b0, c[i][j][1] + b0);
                *(float2*)(d1 + col) = make_float2(c[i][j][2] + b1, c[i][j][3] + b1);
            }
        }
    };
    run_gemm_async(smem, V_ / 32,
                   g_wW_hi + (size_t)o0 * V_, g_wW_lo + (size_t)o0 * V_, V_,
                   g_ctx_hi + co, g_ctx_lo + co, V_, ep);
}

// ---------------------------------------------------------------------------
extern "C" void kernel_launch(void* const* d_in, const int* in_sizes, int n_in,
                              void* d_out, int out_size) {
    const float* x     = (const float*)d_in[0];
    const float* wv    = (const float*)d_in[1];
    const float* bv    = (const float*)d_in[2];
    const float* wk    = (const float*)d_in[3];
    const float* bk    = (const float*)d_in[4];
    const float* gamma = (const float*)d_in[5];
    const float* beta  = (const float*)d_in[6];
    const float* rmean = (const float*)d_in[7];
    const float* rvar  = (const float*)d_in[8];
    const float* wW    = (const float*)d_in[9];
    const float* bW    = (const float*)d_in[10];
    float* out = (float*)d_out;

    cudaFuncSetAttribute(kA, cudaFuncAttributeMaxDynamicSharedMemorySize, SMEM_SZ);
    cudaFuncSetAttribute(kB, cudaFuncAttributeMaxDynamicSharedMemorySize, ASMEM);
    cudaFuncSetAttribute(kD, cudaFuncAttributeMaxDynamicSharedMemorySize, ASMEM);
    cudaFuncSetAttribute(kE, cudaFuncAttributeMaxDynamicSharedMemorySize, ASMEM);

    kW<<<O_ * V_ / 256, 256>>>(wW);
    kA<<<dim3(N_ / 128, (V_ + K_) / 128, B_), 256, SMEM_SZ>>>(x, wv, bv, wk, bk,
                                                              gamma, beta, rmean, rvar);
    kB<<<dim3(N_ / 128, N_ / 128, B_), 256, ASMEM>>>();
    kC_softmax<<<dim3(N_, B_), 256>>>();
    kD<<<dim3(N_ / 128, V_ / 128, B_), 256, ASMEM>>>();
    kE<<<dim3(N_ / 128, O_ / 128, B_), 256, ASMEM>>>(bW, out);
}

// round 12
// speedup vs baseline: 3.2107x; 1.0013x over previous
#include <cuda_runtime.h>
#include <cuda_bf16.h>
#include <cstdint>
#include <math.h>

#define B_  8
#define C_  512
#define N_  4096
#define K_  256
#define V_  256
#define O_  512
#define BN_EPS 1e-5f
#define SIM_SCALE 0.0625f

typedef __nv_bfloat16  bf16;
typedef __nv_bfloat162 bf162;

// ---------------- device scratch (allocation-free) ----------------
__device__ __align__(256) bf16  g_val_hi[(size_t)B_ * V_ * N_];   // [b][v][n]
__device__ __align__(256) bf16  g_val_lo[(size_t)B_ * V_ * N_];
__device__ __align__(256) bf16  g_key_hi[(size_t)B_ * N_ * K_];   // [b][n][k]
__device__ __align__(256) bf16  g_key_lo[(size_t)B_ * N_ * K_];
__device__ __align__(256) bf16  g_ctx_hi[(size_t)B_ * N_ * V_];   // [b][n][v]
__device__ __align__(256) bf16  g_ctx_lo[(size_t)B_ * N_ * V_];
__device__ __align__(256) bf16  g_simh [(size_t)B_ * N_ * N_];    // [b][n][m] softmaxed
__device__ __align__(256) bf16  g_siml [(size_t)B_ * N_ * N_];
__device__ __align__(256) float g_sim  [(size_t)B_ * N_ * N_];    // [b][n][m] logits
__device__ __align__(256) bf16  g_wW_hi[O_ * V_];
__device__ __align__(256) bf16  g_wW_lo[O_ * V_];

// ---------------- common PTX helpers ----------------
__device__ __forceinline__ uint32_t smem_u32(const void* p) {
    uint32_t a;
    asm("{ .reg .u64 t; cvta.to.shared.u64 t, %1; cvt.u32.u64 %0, t; }" : "=r"(a) : "l"(p));
    return a;
}
__device__ __forceinline__ void ldsm4(uint32_t& r0, uint32_t& r1, uint32_t& r2, uint32_t& r3,
                                      uint32_t addr) {
    asm volatile("ldmatrix.sync.aligned.m8n8.x4.shared.b16 {%0,%1,%2,%3}, [%4];"
                 : "=r"(r0), "=r"(r1), "=r"(r2), "=r"(r3) : "r"(addr));
}
__device__ __forceinline__ void mma16816(float* c, uint32_t a0, uint32_t a1, uint32_t a2,
                                         uint32_t a3, uint32_t b0, uint32_t b1) {
    asm volatile(
        "mma.sync.aligned.m16n8k16.row.col.f32.bf16.bf16.f32 "
        "{%0,%1,%2,%3}, {%4,%5,%6,%7}, {%8,%9}, {%0,%1,%2,%3};"
        : "+f"(c[0]), "+f"(c[1]), "+f"(c[2]), "+f"(c[3])
        : "r"(a0), "r"(a1), "r"(a2), "r"(a3), "r"(b0), "r"(b1));
}
__device__ __forceinline__ void cpa16(uint32_t dst, const void* src) {
    asm volatile("cp.async.cg.shared.global [%0], [%1], 16;" :: "r"(dst), "l"(src));
}
// split f32 pair -> packed bf16 hi + packed bf16 lo
__device__ __forceinline__ void split2(float x, float y, bf162& h, bf162& l) {
    h = __floats2bfloat162_rn(x, y);
    l = __floats2bfloat162_rn(x - __bfloat162float(h.x), y - __bfloat162float(h.y));
}
__device__ __forceinline__ void cvt2(float x, float y, uint32_t& h, uint32_t& l) {
    bf162 hh, ll;
    split2(x, y, hh, ll);
    h = *(uint32_t*)&hh;
    l = *(uint32_t*)&ll;
}

// ===========================================================================
// Async GEMM core: 128x128 tile, BK=32, operands are pre-split bf16 hi/lo
// planes in gmem, row-major [row][k], k contiguous. 3-stage cp.async pipe.
// smem stage: AHI(8K) ALO(8K) BHI(8K) BLO(8K) = 32KB; 3 stages = 96KB.
// 2 CTAs/SM (launch_bounds (256,2)); fragment live ranges kept low so the
// kernel fits in 128 regs without spills.
// ===========================================================================
#define ASTAGE 32768u
#define ASMEM  98304

template <class EP>
__device__ __forceinline__ void run_gemm_async(
        char* smem, int nc,
        const bf16* __restrict__ aH, const bf16* __restrict__ aL, int as,
        const bf16* __restrict__ bH, const bf16* __restrict__ bL, int bs, EP ep) {
    const int tid = threadIdx.x;
    const int lane = tid & 31, wid = tid >> 5;
    const int wm0 = (wid >> 2) * 64, wn0 = (wid & 3) * 32;
    const int lr = lane & 15, lc = lane >> 4;
    const uint32_t sb = smem_u32(smem);
    const uint32_t sw = (uint32_t)((lr >> 1) & 3);
    const uint32_t cb0 = ((uint32_t)lc ^ sw) << 4;
    const uint32_t cb1 = ((uint32_t)(2 + lc) ^ sw) << 4;
    const uint32_t aRow = (uint32_t)(wm0 + lr) * 64u;
    const uint32_t bRow = (uint32_t)(wn0 + lr) * 64u;
    float c[4][4][4] = {};

    // copy indexing: each thread moves one 16B chunk per plane-half
    const int r0 = tid >> 2, ck = tid & 3;
    const uint32_t dsw0 = (uint32_t)r0 * 64u + (uint32_t)((ck ^ ((r0 >> 1) & 3)) << 4);
    const bf16* a0 = aH + (size_t)r0 * as + ck * 8;
    const bf16* a1 = aL + (size_t)r0 * as + ck * 8;
    const bf16* b0 = bH + (size_t)r0 * bs + ck * 8;
    const bf16* b1 = bL + (size_t)r0 * bs + ck * 8;

    auto copy = [&](int ch, int stage) {
        const uint32_t st = sb + (uint32_t)stage * ASTAGE;
        const int ko = ch * 32;
        cpa16(st + dsw0,           a0 + ko);
        cpa16(st + dsw0 + 4096u,   a0 + ko + (size_t)64 * as);
        cpa16(st + 8192u  + dsw0,          a1 + ko);
        cpa16(st + 8192u  + dsw0 + 4096u,  a1 + ko + (size_t)64 * as);
        cpa16(st + 16384u + dsw0,          b0 + ko);
        cpa16(st + 16384u + dsw0 + 4096u,  b0 + ko + (size_t)64 * bs);
        cpa16(st + 24576u + dsw0,          b1 + ko);
        cpa16(st + 24576u + dsw0 + 4096u,  b1 + ko + (size_t)64 * bs);
        asm volatile("cp.async.commit_group;");
    };

    auto compute = [&](int stage) {
        const uint32_t st = sb + (uint32_t)stage * ASTAGE;
        const uint32_t ah = st + aRow, al = st + 8192u + aRow;
        const uint32_t bh = st + 16384u + bRow, bl = st + 24576u + bRow;
#pragma unroll
        for (int ks = 0; ks < 2; ++ks) {
            const uint32_t cb = ks ? cb1 : cb0;
            uint32_t AF[4][4], BH[2][4], BX[2][4];
            // hi . hi
#pragma unroll
            for (int i = 0; i < 4; ++i)
                ldsm4(AF[i][0], AF[i][1], AF[i][2], AF[i][3], ah + 1024u * i + cb);
#pragma unroll
            for (int p = 0; p < 2; ++p)
                ldsm4(BH[p][0], BH[p][1], BH[p][2], BH[p][3], bh + 1024u * p + cb);
#pragma unroll
            for (int i = 0; i < 4; ++i)
#pragma unroll
                for (int j = 0; j < 4; ++j)
                    mma16816(c[i][j], AF[i][0], AF[i][1], AF[i][2], AF[i][3],
                             BH[j >> 1][j & 1], BH[j >> 1][(j & 1) + 2]);
            // hi . lo
#pragma unroll
            for (int p = 0; p < 2; ++p)
                ldsm4(BX[p][0], BX[p][1], BX[p][2], BX[p][3], bl + 1024u * p + cb);
#pragma unroll
            for (int i = 0; i < 4; ++i)
#pragma unroll
                for (int j = 0; j < 4; ++j)
                    mma16816(c[i][j], AF[i][0], AF[i][1], AF[i][2], AF[i][3],
                             BX[j >> 1][j & 1], BX[j >> 1][(j & 1) + 2]);
            // lo . hi (overwrite A fragments with lo-plane; BH still live)
#pragma unroll
            for (int i = 0; i < 4; ++i)
                ldsm4(AF[i][0], AF[i][1], AF[i][2], AF[i][3], al + 1024u * i + cb);
#pragma unroll
            for (int i = 0; i < 4; ++i)
#pragma unroll
                for (int j = 0; j < 4; ++j)
                    mma16816(c[i][j], AF[i][0], AF[i][1], AF[i][2], AF[i][3],
                             BH[j >> 1][j & 1], BH[j >> 1][(j & 1) + 2]);
        }
    };

    copy(0, 0);
    copy(1, 1);
#pragma unroll 1
    for (int ch = 0; ch < nc; ++ch) {
        if (ch + 1 < nc) asm volatile("cp.async.wait_group 1;" ::: "memory");
        else             asm volatile("cp.async.wait_group 0;" ::: "memory");
        __syncthreads();
        if (ch + 2 < nc) copy(ch + 2, (ch + 2) % 3);
        compute(ch % 3);
    }
    ep(c, wm0, wn0, lane);
}

// ===========================================================================
// f32-input GEMM core (kA only): 2-stage, converts f32->hi/lo during fill
// ===========================================================================
#define OFF_AHI 0u
#define OFF_ALO 8192u
#define OFF_BHI 16384u
#define OFF_BLO 24576u
#define STAGE_SZ 32768u
#define SMEM_SZ 65536

struct LdK {
    const float* base;
    int stride;
    float4 r[4];
    __device__ __forceinline__ void fetch(int ch, int tid) {
        const float* s = base + ch * 32;
#pragma unroll
        for (int t = 0; t < 2; ++t) {
            int task = tid + t * 256;
            int row = task >> 2, ck = task & 3;
            const float* p = s + (size_t)row * stride + ck * 8;
            r[2 * t]     = *(const float4*)p;
            r[2 * t + 1] = *(const float4*)(p + 4);
        }
    }
    __device__ __forceinline__ void store(char* smem, uint32_t hiOff, uint32_t loOff, int tid) {
#pragma unroll
        for (int t = 0; t < 2; ++t) {
            int task = tid + t * 256;
            int row = task >> 2, ck = task & 3;
            uint32_t off = (uint32_t)row * 64u + (uint32_t)((ck ^ ((row >> 1) & 3)) << 4);
            float4 a = r[2 * t], b = r[2 * t + 1];
            uint32_t h0, h1, h2, h3, l0, l1, l2, l3;
            cvt2(a.x, a.y, h0, l0); cvt2(a.z, a.w, h1, l1);
            cvt2(b.x, b.y, h2, l2); cvt2(b.z, b.w, h3, l3);
            *(uint4*)(smem + hiOff + off) = make_uint4(h0, h1, h2, h3);
            *(uint4*)(smem + loOff + off) = make_uint4(l0, l1, l2, l3);
        }
    }
};
struct LdT {
    const float* base;
    float4 r[4];
    __device__ __forceinline__ void fetch(int ch, int tid) {
        const float* s = base + (size_t)(ch * 32) * N_;
#pragma unroll
        for (int t = 0; t < 4; ++t) {
            int task = tid + t * 256;
            int cc = task >> 5, nq = task & 31;
            r[t] = *(const float4*)(s + (size_t)cc * N_ + nq * 4);
        }
    }
    __device__ __forceinline__ void store(char* smem, uint32_t hiOff, uint32_t loOff, int tid) {
#pragma unroll
        for (int t = 0; t < 4; ++t) {
            int task = tid + t * 256;
            int cc = task >> 5, nq = task & 31;
#pragma unroll
            for (int j = 0; j < 4; ++j) {
                int row = nq * 4 + j;
                float x = (&r[t].x)[j];
                bf16 h = __float2bfloat16_rn(x);
                bf16 l = __float2bfloat16_rn(x - __bfloat162float(h));
                uint32_t off = (uint32_t)row * 64u +
                               (uint32_t)(((cc >> 3) ^ ((row >> 1) & 3)) << 4) + (cc & 7) * 2;
                *(bf16*)(smem + hiOff + off) = h;
                *(bf16*)(smem + loOff + off) = l;
            }
        }
    }
};

__device__ __forceinline__ void mma_pass(uint32_t aBase, uint32_t bBase, uint32_t cb0,
                                         uint32_t cb1, float (&c)[4][4][4]) {
#pragma unroll
    for (int ks = 0; ks < 2; ++ks) {
        const uint32_t cb = ks ? cb1 : cb0;
        uint32_t a[4][4], b[2][4];
#pragma unroll
        for (int i = 0; i < 4; ++i)
            ldsm4(a[i][0], a[i][1], a[i][2], a[i][3], aBase + 1024u * i + cb);
#pragma unroll
        for (int p = 0; p < 2; ++p)
            ldsm4(b[p][0], b[p][1], b[p][2], b[p][3], bBase + 1024u * p + cb);
#pragma unroll
        for (int i = 0; i < 4; ++i)
#pragma unroll
            for (int j = 0; j < 4; ++j)
                mma16816(c[i][j], a[i][0], a[i][1], a[i][2], a[i][3],
                         b[j >> 1][j & 1], b[j >> 1][(j & 1) + 2]);
    }
}

template <class LA, class LB, class EP>
__device__ __forceinline__ void run_gemm(char* smem, int nc, LA& A, LB& Bv, EP ep) {
    const int tid = threadIdx.x;
    const int lane = tid & 31, wid = tid >> 5;
    const int wm0 = (wid >> 2) * 64, wn0 = (wid & 3) * 32;
    const int lr = lane & 15, lc = lane >> 4;
    const uint32_t sb = smem_u32(smem);
    const uint32_t sw = (uint32_t)((lr >> 1) & 3);
    const uint32_t cb0 = ((uint32_t)lc ^ sw) << 4;
    const uint32_t cb1 = ((uint32_t)(2 + lc) ^ sw) << 4;
    const uint32_t aRow = (uint32_t)(wm0 + lr) * 64u;
    const uint32_t bRow = (uint32_t)(wn0 + lr) * 64u;
    float c[4][4][4] = {};

    A.fetch(0, tid); Bv.fetch(0, tid);
    A.store(smem, OFF_AHI, OFF_ALO, tid); Bv.store(smem, OFF_BHI, OFF_BLO, tid);
    __syncthreads();
#pragma unroll 1
    for (int ch = 0; ch < nc; ++ch) {
        const uint32_t st = (ch & 1) ? STAGE_SZ : 0u;
        const bool more = (ch + 1 < nc);
        if (more) { A.fetch(ch + 1, tid); Bv.fetch(ch + 1, tid); }
        mma_pass(sb + st + OFF_AHI + aRow, sb + st + OFF_BHI + bRow, cb0, cb1, c);
        mma_pass(sb + st + OFF_AHI + aRow, sb + st + OFF_BLO + bRow, cb0, cb1, c);
        mma_pass(sb + st + OFF_ALO + aRow, sb + st + OFF_BHI + bRow, cb0, cb1, c);
        if (more) {
            const uint32_t ns = st ^ STAGE_SZ;
            A.store(smem, ns + OFF_AHI, ns + OFF_ALO, tid);
            Bv.store(smem, ns + OFF_BHI, ns + OFF_BLO, tid);
        }
        __syncthreads();
    }
    ep(c, wm0, wn0, lane);
}

// ---------------- kW: pre-split wW into bf16 hi/lo planes ----------------
__global__ void kW(const float* __restrict__ w) {
    int i = blockIdx.x * 256 + threadIdx.x;
    float x = w[i];
    bf16 h = __float2bfloat16_rn(x);
    g_wW_hi[i] = h;
    g_wW_lo[i] = __float2bfloat16_rn(x - __bfloat162float(h));
}

// ---------------- Kernel A: fused value/key projection ----------------
__global__ void __launch_bounds__(256, 1)
kA(const float* __restrict__ x,
   const float* __restrict__ wv, const float* __restrict__ bv,
   const float* __restrict__ wk, const float* __restrict__ bk,
   const float* __restrict__ gamma, const float* __restrict__ beta,
   const float* __restrict__ rmean, const float* __restrict__ rvar) {
    extern __shared__ char smem[];
    const int b = blockIdx.z, n0 = blockIdx.x * 128, ch0 = blockIdx.y * 128;
    const float* wsrc = (ch0 < V_) ? (wv + (size_t)ch0 * C_) : (wk + (size_t)(ch0 - V_) * C_);
    LdK A{wsrc, C_};
    LdT Bv{x + (size_t)b * C_ * N_ + n0};

    auto ep = [&](float (&c)[4][4][4], int wm0, int wn0, int lane) {
        if (ch0 < V_) {
#pragma unroll
            for (int i = 0; i < 4; ++i) {
                int row = ch0 + wm0 + i * 16 + (lane >> 2);
                float b0 = bv[row], b1 = bv[row + 8];
                size_t d0 = ((size_t)b * V_ + row) * N_ + n0;
                size_t d1 = d0 + (size_t)8 * N_;
#pragma unroll
                for (int j = 0; j < 4; ++j) {
                    int col = wn0 + j * 8 + (lane & 3) * 2;
                    bf162 h, l;
                    split2(c[i][j][0] + b0, c[i][j][1] + b0, h, l);
                    *(bf162*)(g_val_hi + d0 + col) = h;
                    *(bf162*)(g_val_lo + d0 + col) = l;
                    split2(c[i][j][2] + b1, c[i][j][3] + b1, h, l);
                    *(bf162*)(g_val_hi + d1 + col) = h;
                    *(bf162*)(g_val_lo + d1 + col) = l;
                }
            }
        } else {
#pragma unroll
            for (int i = 0; i < 4; ++i) {
                int r0 = ch0 - V_ + wm0 + i * 16 + (lane >> 2);
                int r1 = r0 + 8;
                float s0 = gamma[r0] * rsqrtf(rvar[r0] + BN_EPS);
                float h0 = beta[r0] - (rmean[r0] - bk[r0]) * s0;
                float s1 = gamma[r1] * rsqrtf(rvar[r1] + BN_EPS);
                float h1 = beta[r1] - (rmean[r1] - bk[r1]) * s1;
#pragma unroll
                for (int j = 0; j < 4; ++j) {
                    int col = n0 + wn0 + j * 8 + (lane & 3) * 2;
                    size_t kb = ((size_t)b * N_ + col) * K_;
                    float v00 = fmaxf(c[i][j][0] * s0 + h0, 0.f);
                    float v01 = fmaxf(c[i][j][1] * s0 + h0, 0.f);
                    float v10 = fmaxf(c[i][j][2] * s1 + h1, 0.f);
                    float v11 = fmaxf(c[i][j][3] * s1 + h1, 0.f);
                    bf16 t;
                    t = __float2bfloat16_rn(v00); g_key_hi[kb + r0] = t;
                    g_key_lo[kb + r0] = __float2bfloat16_rn(v00 - __bfloat162float(t));
                    t = __float2bfloat16_rn(v01); g_key_hi[kb + K_ + r0] = t;
                    g_key_lo[kb + K_ + r0] = __float2bfloat16_rn(v01 - __bfloat162float(t));
                    t = __float2bfloat16_rn(v10); g_key_hi[kb + r1] = t;
                    g_key_lo[kb + r1] = __float2bfloat16_rn(v10 - __bfloat162float(t));
                    t = __float2bfloat16_rn(v11); g_key_hi[kb + K_ + r1] = t;
                    g_key_lo[kb + K_ + r1] = __float2bfloat16_rn(v11 - __bfloat162float(t));
                }
            }
        }
    };
    run_gemm(smem, C_ / 32, A, Bv, ep);
}

// ---------------- Kernel B: sim = keyT . keyT^T * 1/16 (async) ----------------
__global__ void __launch_bounds__(256, 2) kB() {
    extern __shared__ char smem[];
    const int b = blockIdx.z, m0 = blockIdx.x * 128, n0 = blockIdx.y * 128;
    const size_t kb = (size_t)b * N_ * K_;
    float* simb = g_sim + (size_t)b * N_ * N_;

    auto ep = [&](float (&c)[4][4][4], int wm0, int wn0, int lane) {
#pragma unroll
        for (int i = 0; i < 4; ++i) {
            int row = n0 + wm0 + i * 16 + (lane >> 2);
            float* d0 = simb + (size_t)row * N_ + m0;
            float* d1 = d0 + (size_t)8 * N_;
#pragma unroll
            for (int j = 0; j < 4; ++j) {
                int col = wn0 + j * 8 + (lane & 3) * 2;
                *(float2*)(d0 + col) = make_float2(c[i][j][0] * SIM_SCALE, c[i][j][1] * SIM_SCALE);
                *(float2*)(d1 + col) = make_float2(c[i][j][2] * SIM_SCALE, c[i][j][3] * SIM_SCALE);
            }
        }
    };
    run_gemm_async(smem, K_ / 32,
                   g_key_hi + kb + (size_t)n0 * K_, g_key_lo + kb + (size_t)n0 * K_, K_,
                   g_key_hi + kb + (size_t)m0 * K_, g_key_lo + kb + (size_t)m0 * K_, K_, ep);
}

// ---------------- Kernel C: row softmax, f32 in, bf16 hi/lo out ----------------
__global__ void kC_softmax() {
    const int tid = threadIdx.x;
    const size_t rowo = ((size_t)blockIdx.y * N_ + blockIdx.x) * N_;
    const float4* rowv = (const float4*)(g_sim + rowo);

    float4 d[4];
    float mx = -1e30f;
#pragma unroll
    for (int c = 0; c < 4; ++c) {
        d[c] = rowv[c * 256 + tid];
        mx = fmaxf(mx, fmaxf(fmaxf(d[c].x, d[c].y), fmaxf(d[c].z, d[c].w)));
    }
    __shared__ float sred[8];
#pragma unroll
    for (int o = 16; o; o >>= 1) mx = fmaxf(mx, __shfl_xor_sync(0xffffffffu, mx, o));
    if ((tid & 31) == 0) sred[tid >> 5] = mx;
    __syncthreads();
    {
        float v = sred[tid & 7];
#pragma unroll
        for (int o = 4; o; o >>= 1) v = fmaxf(v, __shfl_xor_sync(0xffffffffu, v, o));
        mx = v;
    }
    __syncthreads();
    float sum = 0.f;
#pragma unroll
    for (int c = 0; c < 4; ++c) {
        d[c].x = __expf(d[c].x - mx); d[c].y = __expf(d[c].y - mx);
        d[c].z = __expf(d[c].z - mx); d[c].w = __expf(d[c].w - mx);
        sum += (d[c].x + d[c].y) + (d[c].z + d[c].w);
    }
#pragma unroll
    for (int o = 16; o; o >>= 1) sum += __shfl_xor_sync(0xffffffffu, sum, o);
    if ((tid & 31) == 0) sred[tid >> 5] = sum;
    __syncthreads();
    {
        float v = sred[tid & 7];
#pragma unroll
        for (int o = 4; o; o >>= 1) v += __shfl_xor_sync(0xffffffffu, v, o);
        sum = v;
    }
    float inv = __frcp_rn(sum);
    bf16* rh = g_simh + rowo;
    bf16* rl = g_siml + rowo;
#pragma unroll
    for (int c = 0; c < 4; ++c) {
        int idx = (c * 256 + tid) * 4;
        float p0 = d[c].x * inv, p1 = d[c].y * inv, p2 = d[c].z * inv, p3 = d[c].w * inv;
        bf162 h0, l0, h1, l1;
        split2(p0, p1, h0, l0);
        split2(p2, p3, h1, l1);
        *(bf162*)(rh + idx)     = h0;
        *(bf162*)(rh + idx + 2) = h1;
        *(bf162*)(rl + idx)     = l0;
        *(bf162*)(rl + idx + 2) = l1;
    }
}

// ---------------- Kernel D: ctxT[n][v] = sum_m sim[n][m]*val[v][m] (async) ----------------
__global__ void __launch_bounds__(256, 2) kD() {
    extern __shared__ char smem[];
    const int b = blockIdx.z, n0 = blockIdx.x * 128, v0 = blockIdx.y * 128;
    const size_t so = (size_t)b * N_ * N_ + (size_t)n0 * N_;
    const size_t vo = (size_t)b * V_ * N_ + (size_t)v0 * N_;

    auto ep = [&](float (&c)[4][4][4], int wm0, int wn0, int lane) {
#pragma unroll
        for (int i = 0; i < 4; ++i) {
            int row = n0 + wm0 + i * 16 + (lane >> 2);
            size_t d0 = ((size_t)b * N_ + row) * V_ + v0;
            size_t d1 = d0 + (size_t)8 * V_;
#pragma unroll
            for (int j = 0; j < 4; ++j) {
                int col = wn0 + j * 8 + (lane & 3) * 2;
                bf162 h, l;
                split2(c[i][j][0], c[i][j][1], h, l);
                *(bf162*)(g_ctx_hi + d0 + col) = h;
                *(bf162*)(g_ctx_lo + d0 + col) = l;
                split2(c[i][j][2], c[i][j][3], h, l);
                *(bf162*)(g_ctx_hi + d1 + col) = h;
                *(bf162*)(g_ctx_lo + d1 + col) = l;
            }
        }
    };
    run_gemm_async(smem, N_ / 32,
                   g_simh + so, g_siml + so, N_,
                   g_val_hi + vo, g_val_lo + vo, N_, ep);
}

// ---------------- Kernel E: out = wW . ctxT^T + bW (async) ----------------
__global__ void __launch_bounds__(256, 2)
kE(const float* __restrict__ bW, float* __restrict__ out) {
    extern __shared__ char smem[];
    const int b = blockIdx.z, n0 = blockIdx.x * 128, o0 = blockIdx.y * 128;
    const size_t co = (size_t)b * N_ * V_ + (size_t)n0 * V_;

    auto ep = [&](float (&c)[4][4][4], int wm0, int wn0, int lane) {
#pragma unroll
        for (int i = 0; i < 4; ++i) {
            int row = o0 + wm0 + i * 16 + (lane >> 2);
            float b0 = bW[row], b1 = bW[row + 8];
            float* d0 = out + ((size_t)b * O_ + row) * N_ + n0;
            float* d1 = d0 + (size_t)8 * N_;
#pragma unroll
            for (int j = 0; j < 4; ++j) {
                int col = wn0 + j * 8 + (lane & 3) * 2;
                *(float2*)(d0 + col) = make_float2(c[i][j][0] + b0, c[i][j][1] + b0);
                *(float2*)(d1 + col) = make_float2(c[i][j][2] + b1, c[i][j][3] + b1);
            }
        }
    };
    run_gemm_async(smem, V_ / 32,
                   g_wW_hi + (size_t)o0 * V_, g_wW_lo + (size_t)o0 * V_, V_,
                   g_ctx_hi + co, g_ctx_lo + co, V_, ep);
}

// ---------------------------------------------------------------------------
extern "C" void kernel_launch(void* const* d_in, const int* in_sizes, int n_in,
                              void* d_out, int out_size) {
    const float* x     = (const float*)d_in[0];
    const float* wv    = (const float*)d_in[1];
    const float* bv    = (const float*)d_in[2];
    const float* wk    = (const float*)d_in[3];
    const float* bk    = (const float*)d_in[4];
    const float* gamma = (const float*)d_in[5];
    const float* beta  = (const float*)d_in[6];
    const float* rmean = (const float*)d_in[7];
    const float* rvar  = (const float*)d_in[8];
    const float* wW    = (const float*)d_in[9];
    const float* bW    = (const float*)d_in[10];
    float* out = (float*)d_out;

    cudaFuncSetAttribute(kA, cudaFuncAttributeMaxDynamicSharedMemorySize, SMEM_SZ);
    cudaFuncSetAttribute(kB, cudaFuncAttributeMaxDynamicSharedMemorySize, ASMEM);
    cudaFuncSetAttribute(kD, cudaFuncAttributeMaxDynamicSharedMemorySize, ASMEM);
    cudaFuncSetAttribute(kE, cudaFuncAttributeMaxDynamicSharedMemorySize, ASMEM);

    kW<<<O_ * V_ / 256, 256>>>(wW);
    kA<<<dim3(N_ / 128, (V_ + K_) / 128, B_), 256, SMEM_SZ>>>(x, wv, bv, wk, bk,
                                                              gamma, beta, rmean, rvar);
    kB<<<dim3(N_ / 128, N_ / 128, B_), 256, ASMEM>>>();
    kC_softmax<<<dim3(N_, B_), 256>>>();
    kD<<<dim3(N_ / 128, V_ / 128, B_), 256, ASMEM>>>();
    kE<<<dim3(N_ / 128, O_ / 128, B_), 256, ASMEM>>>(bW, out);
}

// round 13
// speedup vs baseline: 3.8770x; 1.2075x over previous
#include <cuda_runtime.h>
#include <cuda_bf16.h>
#include <cuda_fp16.h>
#include <cstdint>
#include <math.h>

#define B_  8
#define C_  512
#define N_  4096
#define K_  256
#define V_  256
#define O_  512
#define BN_EPS 1e-5f
#define SIM_SCALE 0.0625f

typedef __nv_bfloat16  bf16;
typedef __nv_bfloat162 bf162;

// ---------------- device scratch (allocation-free) ----------------
__device__ __align__(256) bf16   g_val_hi[(size_t)B_ * V_ * N_];   // [b][v][n]
__device__ __align__(256) bf16   g_val_lo[(size_t)B_ * V_ * N_];
__device__ __align__(256) __half g_key_f16[(size_t)B_ * N_ * K_];  // [b][n][k] fp16
__device__ __align__(256) bf16   g_ctx_hi[(size_t)B_ * N_ * V_];   // [b][n][v]
__device__ __align__(256) bf16   g_ctx_lo[(size_t)B_ * N_ * V_];
__device__ __align__(256) bf16   g_simh [(size_t)B_ * N_ * N_];    // [b][n][m] softmaxed
__device__ __align__(256) bf16   g_siml [(size_t)B_ * N_ * N_];
__device__ __align__(256) float  g_sim  [(size_t)B_ * N_ * N_];    // [b][n][m] logits
__device__ __align__(256) bf16   g_wW_hi[O_ * V_];
__device__ __align__(256) bf16   g_wW_lo[O_ * V_];

// ---------------- common PTX helpers ----------------
__device__ __forceinline__ uint32_t smem_u32(const void* p) {
    uint32_t a;
    asm("{ .reg .u64 t; cvta.to.shared.u64 t, %1; cvt.u32.u64 %0, t; }" : "=r"(a) : "l"(p));
    return a;
}
__device__ __forceinline__ void ldsm4(uint32_t& r0, uint32_t& r1, uint32_t& r2, uint32_t& r3,
                                      uint32_t addr) {
    asm volatile("ldmatrix.sync.aligned.m8n8.x4.shared.b16 {%0,%1,%2,%3}, [%4];"
                 : "=r"(r0), "=r"(r1), "=r"(r2), "=r"(r3) : "r"(addr));
}
__device__ __forceinline__ void mma16816(float* c, uint32_t a0, uint32_t a1, uint32_t a2,
                                         uint32_t a3, uint32_t b0, uint32_t b1) {
    asm volatile(
        "mma.sync.aligned.m16n8k16.row.col.f32.bf16.bf16.f32 "
        "{%0,%1,%2,%3}, {%4,%5,%6,%7}, {%8,%9}, {%0,%1,%2,%3};"
        : "+f"(c[0]), "+f"(c[1]), "+f"(c[2]), "+f"(c[3])
        : "r"(a0), "r"(a1), "r"(a2), "r"(a3), "r"(b0), "r"(b1));
}
__device__ __forceinline__ void mma16816h(float* c, uint32_t a0, uint32_t a1, uint32_t a2,
                                          uint32_t a3, uint32_t b0, uint32_t b1) {
    asm volatile(
        "mma.sync.aligned.m16n8k16.row.col.f32.f16.f16.f32 "
        "{%0,%1,%2,%3}, {%4,%5,%6,%7}, {%8,%9}, {%0,%1,%2,%3};"
        : "+f"(c[0]), "+f"(c[1]), "+f"(c[2]), "+f"(c[3])
        : "r"(a0), "r"(a1), "r"(a2), "r"(a3), "r"(b0), "r"(b1));
}
__device__ __forceinline__ void cpa16(uint32_t dst, const void* src) {
    asm volatile("cp.async.cg.shared.global [%0], [%1], 16;" :: "r"(dst), "l"(src));
}
// split f32 pair -> packed bf16 hi + packed bf16 lo
__device__ __forceinline__ void split2(float x, float y, bf162& h, bf162& l) {
    h = __floats2bfloat162_rn(x, y);
    l = __floats2bfloat162_rn(x - __bfloat162float(h.x), y - __bfloat162float(h.y));
}
__device__ __forceinline__ void cvt2(float x, float y, uint32_t& h, uint32_t& l) {
    bf162 hh, ll;
    split2(x, y, hh, ll);
    h = *(uint32_t*)&hh;
    l = *(uint32_t*)&ll;
}

// ===========================================================================
// 3-pass bf16 async GEMM core (kD, kE): 128x128 tile, BK=32, hi/lo planes.
// stage: AHI(8K) ALO(8K) BHI(8K) BLO(8K) = 32KB; 3 stages = 96KB.
// ===========================================================================
#define ASTAGE 32768u
#define ASMEM  98304

template <class EP>
__device__ __forceinline__ void run_gemm_async(
        char* smem, int nc,
        const bf16* __restrict__ aH, const bf16* __restrict__ aL, int as,
        const bf16* __restrict__ bH, const bf16* __restrict__ bL, int bs, EP ep) {
    const int tid = threadIdx.x;
    const int lane = tid & 31, wid = tid >> 5;
    const int wm0 = (wid >> 2) * 64, wn0 = (wid & 3) * 32;
    const int lr = lane & 15, lc = lane >> 4;
    const uint32_t sb = smem_u32(smem);
    const uint32_t sw = (uint32_t)((lr >> 1) & 3);
    const uint32_t cb0 = ((uint32_t)lc ^ sw) << 4;
    const uint32_t cb1 = ((uint32_t)(2 + lc) ^ sw) << 4;
    const uint32_t aRow = (uint32_t)(wm0 + lr) * 64u;
    const uint32_t bRow = (uint32_t)(wn0 + lr) * 64u;
    float c[4][4][4] = {};

    const int r0 = tid >> 2, ck = tid & 3;
    const uint32_t dsw0 = (uint32_t)r0 * 64u + (uint32_t)((ck ^ ((r0 >> 1) & 3)) << 4);
    const bf16* a0 = aH + (size_t)r0 * as + ck * 8;
    const bf16* a1 = aL + (size_t)r0 * as + ck * 8;
    const bf16* b0 = bH + (size_t)r0 * bs + ck * 8;
    const bf16* b1 = bL + (size_t)r0 * bs + ck * 8;

    auto copy = [&](int ch, int stage) {
        const uint32_t st = sb + (uint32_t)stage * ASTAGE;
        const int ko = ch * 32;
        cpa16(st + dsw0,           a0 + ko);
        cpa16(st + dsw0 + 4096u,   a0 + ko + (size_t)64 * as);
        cpa16(st + 8192u  + dsw0,          a1 + ko);
        cpa16(st + 8192u  + dsw0 + 4096u,  a1 + ko + (size_t)64 * as);
        cpa16(st + 16384u + dsw0,          b0 + ko);
        cpa16(st + 16384u + dsw0 + 4096u,  b0 + ko + (size_t)64 * bs);
        cpa16(st + 24576u + dsw0,          b1 + ko);
        cpa16(st + 24576u + dsw0 + 4096u,  b1 + ko + (size_t)64 * bs);
        asm volatile("cp.async.commit_group;");
    };

    auto compute = [&](int stage) {
        const uint32_t st = sb + (uint32_t)stage * ASTAGE;
        const uint32_t ah = st + aRow, al = st + 8192u + aRow;
        const uint32_t bh = st + 16384u + bRow, bl = st + 24576u + bRow;
#pragma unroll
        for (int ks = 0; ks < 2; ++ks) {
            const uint32_t cb = ks ? cb1 : cb0;
            uint32_t AF[4][4], BH[2][4], BX[2][4];
            // hi . hi
#pragma unroll
            for (int i = 0; i < 4; ++i)
                ldsm4(AF[i][0], AF[i][1], AF[i][2], AF[i][3], ah + 1024u * i + cb);
#pragma unroll
            for (int p = 0; p < 2; ++p)
                ldsm4(BH[p][0], BH[p][1], BH[p][2], BH[p][3], bh + 1024u * p + cb);
#pragma unroll
            for (int i = 0; i < 4; ++i)
#pragma unroll
                for (int j = 0; j < 4; ++j)
                    mma16816(c[i][j], AF[i][0], AF[i][1], AF[i][2], AF[i][3],
                             BH[j >> 1][j & 1], BH[j >> 1][(j & 1) + 2]);
            // hi . lo
#pragma unroll
            for (int p = 0; p < 2; ++p)
                ldsm4(BX[p][0], BX[p][1], BX[p][2], BX[p][3], bl + 1024u * p + cb);
#pragma unroll
            for (int i = 0; i < 4; ++i)
#pragma unroll
                for (int j = 0; j < 4; ++j)
                    mma16816(c[i][j], AF[i][0], AF[i][1], AF[i][2], AF[i][3],
                             BX[j >> 1][j & 1], BX[j >> 1][(j & 1) + 2]);
            // lo . hi (overwrite A fragments with lo-plane; BH still live)
#pragma unroll
            for (int i = 0; i < 4; ++i)
                ldsm4(AF[i][0], AF[i][1], AF[i][2], AF[i][3], al + 1024u * i + cb);
#pragma unroll
            for (int i = 0; i < 4; ++i)
#pragma unroll
                for (int j = 0; j < 4; ++j)
                    mma16816(c[i][j], AF[i][0], AF[i][1], AF[i][2], AF[i][3],
                             BH[j >> 1][j & 1], BH[j >> 1][(j & 1) + 2]);
        }
    };

    copy(0, 0);
    copy(1, 1);
#pragma unroll 1
    for (int ch = 0; ch < nc; ++ch) {
        if (ch + 1 < nc) asm volatile("cp.async.wait_group 1;" ::: "memory");
        else             asm volatile("cp.async.wait_group 0;" ::: "memory");
        __syncthreads();
        if (ch + 2 < nc) copy(ch + 2, (ch + 2) % 3);
        compute(ch % 3);
    }
    ep(c, wm0, wn0, lane);
}

// ===========================================================================
// Single-pass fp16 async GEMM core (kB): 128x128 tile, BK=32, one plane each.
// stage: A(8K) B(8K) = 16KB; 3 stages = 48KB. 16 mma + 8 ldsm per k-step.
// ===========================================================================
#define ASTAGE1 16384u
#define ASMEM1  49152

template <class EP>
__device__ __forceinline__ void run_gemm_async_h(
        char* smem, int nc,
        const __half* __restrict__ aP, int as,
        const __half* __restrict__ bP, int bs, EP ep) {
    const int tid = threadIdx.x;
    const int lane = tid & 31, wid = tid >> 5;
    const int wm0 = (wid >> 2) * 64, wn0 = (wid & 3) * 32;
    const int lr = lane & 15, lc = lane >> 4;
    const uint32_t sb = smem_u32(smem);
    const uint32_t sw = (uint32_t)((lr >> 1) & 3);
    const uint32_t cb0 = ((uint32_t)lc ^ sw) << 4;
    const uint32_t cb1 = ((uint32_t)(2 + lc) ^ sw) << 4;
    const uint32_t aRow = (uint32_t)(wm0 + lr) * 64u;
    const uint32_t bRow = (uint32_t)(wn0 + lr) * 64u;
    float c[4][4][4] = {};

    const int r0 = tid >> 2, ck = tid & 3;
    const uint32_t dsw0 = (uint32_t)r0 * 64u + (uint32_t)((ck ^ ((r0 >> 1) & 3)) << 4);
    const __half* a0 = aP + (size_t)r0 * as + ck * 8;
    const __half* b0 = bP + (size_t)r0 * bs + ck * 8;

    auto copy = [&](int ch, int stage) {
        const uint32_t st = sb + (uint32_t)stage * ASTAGE1;
        const int ko = ch * 32;
        cpa16(st + dsw0,                   a0 + ko);
        cpa16(st + dsw0 + 4096u,           a0 + ko + (size_t)64 * as);
        cpa16(st + 8192u + dsw0,           b0 + ko);
        cpa16(st + 8192u + dsw0 + 4096u,   b0 + ko + (size_t)64 * bs);
        asm volatile("cp.async.commit_group;");
    };

    auto compute = [&](int stage) {
        const uint32_t st = sb + (uint32_t)stage * ASTAGE1;
        const uint32_t ah = st + aRow;
        const uint32_t bh = st + 8192u + bRow;
#pragma unroll
        for (int ks = 0; ks < 2; ++ks) {
            const uint32_t cb = ks ? cb1 : cb0;
            uint32_t AF[4][4], BF[2][4];
#pragma unroll
            for (int i = 0; i < 4; ++i)
                ldsm4(AF[i][0], AF[i][1], AF[i][2], AF[i][3], ah + 1024u * i + cb);
#pragma unroll
            for (int p = 0; p < 2; ++p)
                ldsm4(BF[p][0], BF[p][1], BF[p][2], BF[p][3], bh + 1024u * p + cb);
#pragma unroll
            for (int i = 0; i < 4; ++i)
#pragma unroll
                for (int j = 0; j < 4; ++j)
                    mma16816h(c[i][j], AF[i][0], AF[i][1], AF[i][2], AF[i][3],
                              BF[j >> 1][j & 1], BF[j >> 1][(j & 1) + 2]);
        }
    };

    copy(0, 0);
    copy(1, 1);
#pragma unroll 1
    for (int ch = 0; ch < nc; ++ch) {
        if (ch + 1 < nc) asm volatile("cp.async.wait_group 1;" ::: "memory");
        else             asm volatile("cp.async.wait_group 0;" ::: "memory");
        __syncthreads();
        if (ch + 2 < nc) copy(ch + 2, (ch + 2) % 3);
        compute(ch % 3);
    }
    ep(c, wm0, wn0, lane);
}

// ===========================================================================
// f32-input GEMM core (kA only): 2-stage, converts f32->hi/lo during fill
// ===========================================================================
#define OFF_AHI 0u
#define OFF_ALO 8192u
#define OFF_BHI 16384u
#define OFF_BLO 24576u
#define STAGE_SZ 32768u
#define SMEM_SZ 65536

struct LdK {
    const float* base;
    int stride;
    float4 r[4];
    __device__ __forceinline__ void fetch(int ch, int tid) {
        const float* s = base + ch * 32;
#pragma unroll
        for (int t = 0; t < 2; ++t) {
            int task = tid + t * 256;
            int row = task >> 2, ck = task & 3;
            const float* p = s + (size_t)row * stride + ck * 8;
            r[2 * t]     = *(const float4*)p;
            r[2 * t + 1] = *(const float4*)(p + 4);
        }
    }
    __device__ __forceinline__ void store(char* smem, uint32_t hiOff, uint32_t loOff, int tid) {
#pragma unroll
        for (int t = 0; t < 2; ++t) {
            int task = tid + t * 256;
            int row = task >> 2, ck = task & 3;
            uint32_t off = (uint32_t)row * 64u + (uint32_t)((ck ^ ((row >> 1) & 3)) << 4);
            float4 a = r[2 * t], b = r[2 * t + 1];
            uint32_t h0, h1, h2, h3, l0, l1, l2, l3;
            cvt2(a.x, a.y, h0, l0); cvt2(a.z, a.w, h1, l1);
            cvt2(b.x, b.y, h2, l2); cvt2(b.z, b.w, h3, l3);
            *(uint4*)(smem + hiOff + off) = make_uint4(h0, h1, h2, h3);
            *(uint4*)(smem + loOff + off) = make_uint4(l0, l1, l2, l3);
        }
    }
};
struct LdT {
    const float* base;
    float4 r[4];
    __device__ __forceinline__ void fetch(int ch, int tid) {
        const float* s = base + (size_t)(ch * 32) * N_;
#pragma unroll
        for (int t = 0; t < 4; ++t) {
            int task = tid + t * 256;
            int cc = task >> 5, nq = task & 31;
            r[t] = *(const float4*)(s + (size_t)cc * N_ + nq * 4);
        }
    }
    __device__ __forceinline__ void store(char* smem, uint32_t hiOff, uint32_t loOff, int tid) {
#pragma unroll
        for (int t = 0; t < 4; ++t) {
            int task = tid + t * 256;
            int cc = task >> 5, nq = task & 31;
#pragma unroll
            for (int j = 0; j < 4; ++j) {
                int row = nq * 4 + j;
                float x = (&r[t].x)[j];
                bf16 h = __float2bfloat16_rn(x);
                bf16 l = __float2bfloat16_rn(x - __bfloat162float(h));
                uint32_t off = (uint32_t)row * 64u +
                               (uint32_t)(((cc >> 3) ^ ((row >> 1) & 3)) << 4) + (cc & 7) * 2;
                *(bf16*)(smem + hiOff + off) = h;
                *(bf16*)(smem + loOff + off) = l;
            }
        }
    }
};

__device__ __forceinline__ void mma_pass(uint32_t aBase, uint32_t bBase, uint32_t cb0,
                                         uint32_t cb1, float (&c)[4][4][4]) {
#pragma unroll
    for (int ks = 0; ks < 2; ++ks) {
        const uint32_t cb = ks ? cb1 : cb0;
        uint32_t a[4][4], b[2][4];
#pragma unroll
        for (int i = 0; i < 4; ++i)
            ldsm4(a[i][0], a[i][1], a[i][2], a[i][3], aBase + 1024u * i + cb);
#pragma unroll
        for (int p = 0; p < 2; ++p)
            ldsm4(b[p][0], b[p][1], b[p][2], b[p][3], bBase + 1024u * p + cb);
#pragma unroll
        for (int i = 0; i < 4; ++i)
#pragma unroll
            for (int j = 0; j < 4; ++j)
                mma16816(c[i][j], a[i][0], a[i][1], a[i][2], a[i][3],
                         b[j >> 1][j & 1], b[j >> 1][(j & 1) + 2]);
    }
}

template <class LA, class LB, class EP>
__device__ __forceinline__ void run_gemm(char* smem, int nc, LA& A, LB& Bv, EP ep) {
    const int tid = threadIdx.x;
    const int lane = tid & 31, wid = tid >> 5;
    const int wm0 = (wid >> 2) * 64, wn0 = (wid & 3) * 32;
    const int lr = lane & 15, lc = lane >> 4;
    const uint32_t sb = smem_u32(smem);
    const uint32_t sw = (uint32_t)((lr >> 1) & 3);
    const uint32_t cb0 = ((uint32_t)lc ^ sw) << 4;
    const uint32_t cb1 = ((uint32_t)(2 + lc) ^ sw) << 4;
    const uint32_t aRow = (uint32_t)(wm0 + lr) * 64u;
    const uint32_t bRow = (uint32_t)(wn0 + lr) * 64u;
    float c[4][4][4] = {};

    A.fetch(0, tid); Bv.fetch(0, tid);
    A.store(smem, OFF_AHI, OFF_ALO, tid); Bv.store(smem, OFF_BHI, OFF_BLO, tid);
    __syncthreads();
#pragma unroll 1
    for (int ch = 0; ch < nc; ++ch) {
        const uint32_t st = (ch & 1) ? STAGE_SZ : 0u;
        const bool more = (ch + 1 < nc);
        if (more) { A.fetch(ch + 1, tid); Bv.fetch(ch + 1, tid); }
        mma_pass(sb + st + OFF_AHI + aRow, sb + st + OFF_BHI + bRow, cb0, cb1, c);
        mma_pass(sb + st + OFF_AHI + aRow, sb + st + OFF_BLO + bRow, cb0, cb1, c);
        mma_pass(sb + st + OFF_ALO + aRow, sb + st + OFF_BHI + bRow, cb0, cb1, c);
        if (more) {
            const uint32_t ns = st ^ STAGE_SZ;
            A.store(smem, ns + OFF_AHI, ns + OFF_ALO, tid);
            Bv.store(smem, ns + OFF_BHI, ns + OFF_BLO, tid);
        }
        __syncthreads();
    }
    ep(c, wm0, wn0, lane);
}

// ---------------- kW: pre-split wW into bf16 hi/lo planes ----------------
__global__ void kW(const float* __restrict__ w) {
    int i = blockIdx.x * 256 + threadIdx.x;
    float x = w[i];
    bf16 h = __float2bfloat16_rn(x);
    g_wW_hi[i] = h;
    g_wW_lo[i] = __float2bfloat16_rn(x - __bfloat162float(h));
}

// ---------------- Kernel A: fused value/key projection ----------------
__global__ void __launch_bounds__(256, 1)
kA(const float* __restrict__ x,
   const float* __restrict__ wv, const float* __restrict__ bv,
   const float* __restrict__ wk, const float* __restrict__ bk,
   const float* __restrict__ gamma, const float* __restrict__ beta,
   const float* __restrict__ rmean, const float* __restrict__ rvar) {
    extern __shared__ char smem[];
    const int b = blockIdx.z, n0 = blockIdx.x * 128, ch0 = blockIdx.y * 128;
    const float* wsrc = (ch0 < V_) ? (wv + (size_t)ch0 * C_) : (wk + (size_t)(ch0 - V_) * C_);
    LdK A{wsrc, C_};
    LdT Bv{x + (size_t)b * C_ * N_ + n0};

    auto ep = [&](float (&c)[4][4][4], int wm0, int wn0, int lane) {
        if (ch0 < V_) {
#pragma unroll
            for (int i = 0; i < 4; ++i) {
                int row = ch0 + wm0 + i * 16 + (lane >> 2);
                float b0 = bv[row], b1 = bv[row + 8];
                size_t d0 = ((size_t)b * V_ + row) * N_ + n0;
                size_t d1 = d0 + (size_t)8 * N_;
#pragma unroll
                for (int j = 0; j < 4; ++j) {
                    int col = wn0 + j * 8 + (lane & 3) * 2;
                    bf162 h, l;
                    split2(c[i][j][0] + b0, c[i][j][1] + b0, h, l);
                    *(bf162*)(g_val_hi + d0 + col) = h;
                    *(bf162*)(g_val_lo + d0 + col) = l;
                    split2(c[i][j][2] + b1, c[i][j][3] + b1, h, l);
                    *(bf162*)(g_val_hi + d1 + col) = h;
                    *(bf162*)(g_val_lo + d1 + col) = l;
                }
            }
        } else {
#pragma unroll
            for (int i = 0; i < 4; ++i) {
                int r0 = ch0 - V_ + wm0 + i * 16 + (lane >> 2);
                int r1 = r0 + 8;
                float s0 = gamma[r0] * rsqrtf(rvar[r0] + BN_EPS);
                float h0 = beta[r0] - (rmean[r0] - bk[r0]) * s0;
                float s1 = gamma[r1] * rsqrtf(rvar[r1] + BN_EPS);
                float h1 = beta[r1] - (rmean[r1] - bk[r1]) * s1;
#pragma unroll
                for (int j = 0; j < 4; ++j) {
                    int col = n0 + wn0 + j * 8 + (lane & 3) * 2;
                    size_t kb = ((size_t)b * N_ + col) * K_;
                    g_key_f16[kb + r0]      = __float2half_rn(fmaxf(c[i][j][0] * s0 + h0, 0.f));
                    g_key_f16[kb + K_ + r0] = __float2half_rn(fmaxf(c[i][j][1] * s0 + h0, 0.f));
                    g_key_f16[kb + r1]      = __float2half_rn(fmaxf(c[i][j][2] * s1 + h1, 0.f));
                    g_key_f16[kb + K_ + r1] = __float2half_rn(fmaxf(c[i][j][3] * s1 + h1, 0.f));
                }
            }
        }
    };
    run_gemm(smem, C_ / 32, A, Bv, ep);
}

// ---------------- Kernel B: sim = key . key^T * 1/16 (fp16 single-pass) ----------------
__global__ void __launch_bounds__(256, 2) kB() {
    extern __shared__ char smem[];
    const int b = blockIdx.z, m0 = blockIdx.x * 128, n0 = blockIdx.y * 128;
    const size_t kb = (size_t)b * N_ * K_;
    float* simb = g_sim + (size_t)b * N_ * N_;

    auto ep = [&](float (&c)[4][4][4], int wm0, int wn0, int lane) {
#pragma unroll
        for (int i = 0; i < 4; ++i) {
            int row = n0 + wm0 + i * 16 + (lane >> 2);
            float* d0 = simb + (size_t)row * N_ + m0;
            float* d1 = d0 + (size_t)8 * N_;
#pragma unroll
            for (int j = 0; j < 4; ++j) {
                int col = wn0 + j * 8 + (lane & 3) * 2;
                *(float2*)(d0 + col) = make_float2(c[i][j][0] * SIM_SCALE, c[i][j][1] * SIM_SCALE);
                *(float2*)(d1 + col) = make_float2(c[i][j][2] * SIM_SCALE, c[i][j][3] * SIM_SCALE);
            }
        }
    };
    run_gemm_async_h(smem, K_ / 32,
                     g_key_f16 + kb + (size_t)n0 * K_, K_,
                     g_key_f16 + kb + (size_t)m0 * K_, K_, ep);
}

// ---------------- Kernel C: row softmax, f32 in, bf16 hi/lo out ----------------
__global__ void kC_softmax() {
    const int tid = threadIdx.x;
    const size_t rowo = ((size_t)blockIdx.y * N_ + blockIdx.x) * N_;
    const float4* rowv = (const float4*)(g_sim + rowo);

    float4 d[4];
    float mx = -1e30f;
#pragma unroll
    for (int c = 0; c < 4; ++c) {
        d[c] = rowv[c * 256 + tid];
        mx = fmaxf(mx, fmaxf(fmaxf(d[c].x, d[c].y), fmaxf(d[c].z, d[c].w)));
    }
    __shared__ float sred[8];
#pragma unroll
    for (int o = 16; o; o >>= 1) mx = fmaxf(mx, __shfl_xor_sync(0xffffffffu, mx, o));
    if ((tid & 31) == 0) sred[tid >> 5] = mx;
    __syncthreads();
    {
        float v = sred[tid & 7];
#pragma unroll
        for (int o = 4; o; o >>= 1) v = fmaxf(v, __shfl_xor_sync(0xffffffffu, v, o));
        mx = v;
    }
    __syncthreads();
    float sum = 0.f;
#pragma unroll
    for (int c = 0; c < 4; ++c) {
        d[c].x = __expf(d[c].x - mx); d[c].y = __expf(d[c].y - mx);
        d[c].z = __expf(d[c].z - mx); d[c].w = __expf(d[c].w - mx);
        sum += (d[c].x + d[c].y) + (d[c].z + d[c].w);
    }
#pragma unroll
    for (int o = 16; o; o >>= 1) sum += __shfl_xor_sync(0xffffffffu, sum, o);
    if ((tid & 31) == 0) sred[tid >> 5] = sum;
    __syncthreads();
    {
        float v = sred[tid & 7];
#pragma unroll
        for (int o = 4; o; o >>= 1) v += __shfl_xor_sync(0xffffffffu, v, o);
        sum = v;
    }
    float inv = __frcp_rn(sum);
    bf16* rh = g_simh + rowo;
    bf16* rl = g_siml + rowo;
#pragma unroll
    for (int c = 0; c < 4; ++c) {
        int idx = (c * 256 + tid) * 4;
        float p0 = d[c].x * inv, p1 = d[c].y * inv, p2 = d[c].z * inv, p3 = d[c].w * inv;
        bf162 h0, l0, h1, l1;
        split2(p0, p1, h0, l0);
        split2(p2, p3, h1, l1);
        *(bf162*)(rh + idx)     = h0;
        *(bf162*)(rh + idx + 2) = h1;
        *(bf162*)(rl + idx)     = l0;
        *(bf162*)(rl + idx + 2) = l1;
    }
}

// ---------------- Kernel D: ctxT[n][v] = sum_m sim[n][m]*val[v][m] (3-pass bf16) ----------------
__global__ void __launch_bounds__(256, 2) kD() {
    extern __shared__ char smem[];
    const int b = blockIdx.z, n0 = blockIdx.x * 128, v0 = blockIdx.y * 128;
    const size_t so = (size_t)b * N_ * N_ + (size_t)n0 * N_;
    const size_t vo = (size_t)b * V_ * N_ + (size_t)v0 * N_;

    auto ep = [&](float (&c)[4][4][4], int wm0, int wn0, int lane) {
#pragma unroll
        for (int i = 0; i < 4; ++i) {
            int row = n0 + wm0 + i * 16 + (lane >> 2);
            size_t d0 = ((size_t)b * N_ + row) * V_ + v0;
            size_t d1 = d0 + (size_t)8 * V_;
#pragma unroll
            for (int j = 0; j < 4; ++j) {
                int col = wn0 + j * 8 + (lane & 3) * 2;
                bf162 h, l;
                split2(c[i][j][0], c[i][j][1], h, l);
                *(bf162*)(g_ctx_hi + d0 + col) = h;
                *(bf162*)(g_ctx_lo + d0 + col) = l;
                split2(c[i][j][2], c[i][j][3], h, l);
                *(bf162*)(g_ctx_hi + d1 + col) = h;
                *(bf162*)(g_ctx_lo + d1 + col) = l;
            }
        }
    };
    run_gemm_async(smem, N_ / 32,
                   g_simh + so, g_siml + so, N_,
                   g_val_hi + vo, g_val_lo + vo, N_, ep);
}

// ---------------- Kernel E: out = wW . ctxT^T + bW (3-pass bf16) ----------------
__global__ void __launch_bounds__(256, 2)
kE(const float* __restrict__ bW, float* __restrict__ out) {
    extern __shared__ char smem[];
    const int b = blockIdx.z, n0 = blockIdx.x * 128, o0 = blockIdx.y * 128;
    const size_t co = (size_t)b * N_ * V_ + (size_t)n0 * V_;

    auto ep = [&](float (&c)[4][4][4], int wm0, int wn0, int lane) {
#pragma unroll
        for (int i = 0; i < 4; ++i) {
            int row = o0 + wm0 + i * 16 + (lane >> 2);
            float b0 = bW[row], b1 = bW[row + 8];
            float* d0 = out + ((size_t)b * O_ + row) * N_ + n0;
            float* d1 = d0 + (size_t)8 * N_;
#pragma unroll
            for (int j = 0; j < 4; ++j) {
                int col = wn0 + j * 8 + (lane & 3) * 2;
                *(float2*)(d0 + col) = make_float2(c[i][j][0] + b0, c[i][j][1] + b0);
                *(float2*)(d1 + col) = make_float2(c[i][j][2] + b1, c[i][j][3] + b1);
            }
        }
    };
    run_gemm_async(smem, V_ / 32,
                   g_wW_hi + (size_t)o0 * V_, g_wW_lo + (size_t)o0 * V_, V_,
                   g_ctx_hi + co, g_ctx_lo + co, V_, ep);
}

// ---------------------------------------------------------------------------
extern "C" void kernel_launch(void* const* d_in, const int* in_sizes, int n_in,
                              void* d_out, int out_size) {
    const float* x     = (const float*)d_in[0];
    const float* wv    = (const float*)d_in[1];
    const float* bv    = (const float*)d_in[2];
    const float* wk    = (const float*)d_in[3];
    const float* bk    = (const float*)d_in[4];
    const float* gamma = (const float*)d_in[5];
    const float* beta  = (const float*)d_in[6];
    const float* rmean = (const float*)d_in[7];
    const float* rvar  = (const float*)d_in[8];
    const float* wW    = (const float*)d_in[9];
    const float* bW    = (const float*)d_in[10];
    float* out = (float*)d_out;

    cudaFuncSetAttribute(kA, cudaFuncAttributeMaxDynamicSharedMemorySize, SMEM_SZ);
    cudaFuncSetAttribute(kB, cudaFuncAttributeMaxDynamicSharedMemorySize, ASMEM1);
    cudaFuncSetAttribute(kD, cudaFuncAttributeMaxDynamicSharedMemorySize, ASMEM);
    cudaFuncSetAttribute(kE, cudaFuncAttributeMaxDynamicSharedMemorySize, ASMEM);

    kW<<<O_ * V_ / 256, 256>>>(wW);
    kA<<<dim3(N_ / 128, (V_ + K_) / 128, B_), 256, SMEM_SZ>>>(x, wv, bv, wk, bk,
                                                              gamma, beta, rmean, rvar);
    kB<<<dim3(N_ / 128, N_ / 128, B_), 256, ASMEM1>>>();
    kC_softmax<<<dim3(N_, B_), 256>>>();
    kD<<<dim3(N_ / 128, V_ / 128, B_), 256, ASMEM>>>();
    kE<<<dim3(N_ / 128, O_ / 128, B_), 256, ASMEM>>>(bW, out);
}